// round 1
// baseline (speedup 1.0000x reference)
#include <cuda_runtime.h>
#include <math.h>

#define NN   8192
#define BB   16
#define IND  2
#define HH   64
#define FF   66            // IN_DIM + HID
#define CC   (FF*BB)       // 1056 floats per node row
#define CC4  (CC/4)        // 264 float4 per node row
#define EE   131072
#define NMAT 5

// ---------------- device scratch (static: no allocation allowed) ------------
__device__ float g_X[(size_t)10*NN*CC];          // 10 diffusion buffers (0..4 gate, 5..9 cand)
__device__ float g_U[(size_t)BB*NN*HH];          // update gate u
__device__ int   g_cnt[2][NN];
__device__ int   g_cur[2][NN];
__device__ int   g_ptr[2][NN+1];
__device__ int   g_eidx[2][EE];
__device__ int   g_ccol[2][EE];
__device__ float g_cval[2][EE];

// ---------------- CSR build (deterministic) ---------------------------------
__global__ void k_zero()
{
    int i = blockIdx.x*blockDim.x + threadIdx.x;
    if (i < NN) { g_cnt[0][i]=0; g_cnt[1][i]=0; g_cur[0][i]=0; g_cur[1][i]=0; }
}

__global__ void k_count(const int* __restrict__ src, const int* __restrict__ dst)
{
    int e = blockIdx.x*blockDim.x + threadIdx.x;
    if (e < EE) {
        atomicAdd(&g_cnt[0][src[e]], 1);
        atomicAdd(&g_cnt[1][dst[e]], 1);
    }
}

__global__ void k_scan()   // 1 block, 1024 threads, both matrices
{
    __shared__ int s[1024];
    int tid = threadIdx.x;
    for (int m = 0; m < 2; m++) {
        int base = tid*8;
        int c[8];
        int s_local = 0;
        #pragma unroll
        for (int j = 0; j < 8; j++) { c[j] = g_cnt[m][base+j]; s_local += c[j]; }
        s[tid] = s_local;
        __syncthreads();
        for (int off = 1; off < 1024; off <<= 1) {
            int v = (tid >= off) ? s[tid-off] : 0;
            __syncthreads();
            s[tid] += v;
            __syncthreads();
        }
        int run = s[tid] - s_local;   // exclusive prefix
        #pragma unroll
        for (int j = 0; j < 8; j++) { g_ptr[m][base+j] = run; run += c[j]; }
        if (tid == 1023) g_ptr[m][NN] = run;
        __syncthreads();
    }
}

__global__ void k_scatter(const int* __restrict__ src, const int* __restrict__ dst)
{
    int e = blockIdx.x*blockDim.x + threadIdx.x;
    if (e < EE) {
        int r = src[e];
        int p = g_ptr[0][r] + atomicAdd(&g_cur[0][r], 1);
        g_eidx[0][p] = e;
        r = dst[e];
        p = g_ptr[1][r] + atomicAdd(&g_cur[1][r], 1);
        g_eidx[1][p] = e;
    }
}

__global__ void k_sortfill(const int* __restrict__ src, const int* __restrict__ dst,
                           const float* __restrict__ v1, const float* __restrict__ v2)
{
    int r = blockIdx.x*blockDim.x + threadIdx.x;
    if (r >= NN) return;
    for (int m = 0; m < 2; m++) {
        int beg = g_ptr[m][r], end = g_ptr[m][r+1];
        // insertion sort by edge id -> fully deterministic accumulation order
        for (int i = beg+1; i < end; i++) {
            int key = g_eidx[m][i];
            int j = i-1;
            while (j >= beg && g_eidx[m][j] > key) { g_eidx[m][j+1] = g_eidx[m][j]; j--; }
            g_eidx[m][j+1] = key;
        }
        for (int i = beg; i < end; i++) {
            int e = g_eidx[m][i];
            if (m == 0) { g_ccol[0][i] = dst[e]; g_cval[0][i] = v1[e]; }
            else        { g_ccol[1][i] = src[e]; g_cval[1][i] = v2[e]; }
        }
    }
}

// ---------------- build x0 ---------------------------------------------------
// X layout: X[n][b*FF + f]  (per-node contiguous 1056 floats)
__global__ void k_build_x0(const float* __restrict__ inputs, const float* __restrict__ state)
{
    size_t idx = (size_t)blockIdx.x*blockDim.x + threadIdx.x;     // covers NN*CC exactly
    int n = (int)(idx / CC);
    int c = (int)(idx - (size_t)n*CC);
    int b = c / FF, f = c - b*FF;
    float v = (f < IND) ? inputs[(size_t)b*NN*IND + (size_t)n*IND + f]
                        : state [(size_t)b*NN*HH  + (size_t)n*HH  + (f-IND)];
    g_X[idx] = v;
    if (f < IND) g_X[(size_t)5*NN*CC + idx] = v;    // input part of candidate x0
}

// ---------------- SPMM:  Y = alpha * A_m X  + beta * Z ----------------------
__global__ void __launch_bounds__(256) k_spmm(int m, int xi, int yi, int zi,
                                              float alpha, float beta)
{
    const float4* __restrict__ X = (const float4*)(g_X + (size_t)xi*NN*CC);
    float4*       __restrict__ Y = (float4*)      (g_X + (size_t)yi*NN*CC);
    const float4* Z = (zi >= 0) ? (const float4*)(g_X + (size_t)zi*NN*CC) : nullptr;

    int r   = blockIdx.x;
    int beg = g_ptr[m][r], end = g_ptr[m][r+1];
    int tid = threadIdx.x;

    __shared__ int   scol[64];
    __shared__ float sval[64];

    float4 acc0 = make_float4(0.f,0.f,0.f,0.f);
    float4 acc1 = make_float4(0.f,0.f,0.f,0.f);

    for (int cb = beg; cb < end; cb += 64) {
        int cnt = min(64, end - cb);
        if (tid < cnt) { scol[tid] = g_ccol[m][cb+tid]; sval[tid] = g_cval[m][cb+tid]; }
        __syncthreads();
        for (int j = 0; j < cnt; j++) {
            size_t base = (size_t)scol[j]*CC4;
            float w = sval[j];
            float4 xv = X[base + tid];
            acc0.x += w*xv.x; acc0.y += w*xv.y; acc0.z += w*xv.z; acc0.w += w*xv.w;
            if (tid < CC4-256) {
                float4 x2 = X[base + 256 + tid];
                acc1.x += w*x2.x; acc1.y += w*x2.y; acc1.z += w*x2.z; acc1.w += w*x2.w;
            }
        }
        __syncthreads();
    }

    size_t yb = (size_t)r*CC4;
    float4 o;
    o.x = alpha*acc0.x; o.y = alpha*acc0.y; o.z = alpha*acc0.z; o.w = alpha*acc0.w;
    if (Z) { float4 z = Z[yb+tid]; o.x += beta*z.x; o.y += beta*z.y; o.z += beta*z.z; o.w += beta*z.w; }
    Y[yb + tid] = o;
    if (tid < CC4-256) {
        o.x = alpha*acc1.x; o.y = alpha*acc1.y; o.z = alpha*acc1.z; o.w = alpha*acc1.w;
        if (Z) { float4 z = Z[yb+256+tid]; o.x += beta*z.x; o.y += beta*z.y; o.z += beta*z.z; o.w += beta*z.w; }
        Y[yb + 256 + tid] = o;
    }
}

// ---------------- gate GEMM: Z = xstk @ W_gate + b ; sigmoid; fused gating ---
// rows = b*NN + n ; cols o in [0,128) ; K = 330 = 5 mats * 66, BK = 33
__global__ void __launch_bounds__(256) k_gemm_gate(const float* __restrict__ Wg,
                                                   const float* __restrict__ bg,
                                                   const float* __restrict__ state)
{
    __shared__ float As[33][128];
    __shared__ float Bs[33][128];

    int row0 = blockIdx.x * 128;
    int b  = row0 / NN;
    int n0 = row0 - b*NN;
    int tid = threadIdx.x;
    int tx = tid & 15, ty = tid >> 4;

    float acc[8][8];
    #pragma unroll
    for (int i = 0; i < 8; i++)
        #pragma unroll
        for (int j = 0; j < 8; j++) acc[i][j] = 0.f;

    for (int m = 0; m < NMAT; m++) {
        const float* Xm = g_X + (size_t)m*NN*CC;
        for (int k0 = 0; k0 < FF; k0 += 33) {
            for (int idx = tid; idx < 128*33; idx += 256) {
                int rr = idx / 33, fl = idx - rr*33;
                As[fl][rr] = Xm[(size_t)(n0+rr)*CC + b*FF + k0 + fl];
            }
            for (int idx = tid; idx < 33*128; idx += 256) {
                int fl = idx >> 7, o = idx & 127;
                Bs[fl][o] = Wg[((k0+fl)*NMAT + m)*(2*HH) + o];
            }
            __syncthreads();
            #pragma unroll 3
            for (int kk = 0; kk < 33; kk++) {
                float a[8], bv[8];
                *(float4*)&a[0]  = *(const float4*)&As[kk][ty*8];
                *(float4*)&a[4]  = *(const float4*)&As[kk][ty*8+4];
                *(float4*)&bv[0] = *(const float4*)&Bs[kk][tx*8];
                *(float4*)&bv[4] = *(const float4*)&Bs[kk][tx*8+4];
                #pragma unroll
                for (int i = 0; i < 8; i++)
                    #pragma unroll
                    for (int j = 0; j < 8; j++)
                        acc[i][j] += a[i]*bv[j];
            }
            __syncthreads();
        }
    }

    #pragma unroll
    for (int i = 0; i < 8; i++) {
        int rr = ty*8 + i;
        int n  = n0 + rr;
        int row = row0 + rr;
        #pragma unroll
        for (int j = 0; j < 8; j++) {
            int o = tx*8 + j;
            float z = acc[i][j] + bg[o];
            float s = 1.f/(1.f + expf(-z));
            if (o < HH) {   // reset gate: write r*state into candidate x0
                float rs = s * state[(size_t)b*NN*HH + (size_t)n*HH + o];
                g_X[(size_t)5*NN*CC + (size_t)n*CC + b*FF + IND + o] = rs;
            } else {        // update gate
                g_U[(size_t)row*HH + (o-HH)] = s;
            }
        }
    }
}

// ---------------- candidate GEMM + GRU combine -------------------------------
__global__ void __launch_bounds__(256) k_gemm_cand(const float* __restrict__ Wc,
                                                   const float* __restrict__ bc,
                                                   const float* __restrict__ state,
                                                   float* __restrict__ out, int dup)
{
    __shared__ float As[33][128];
    __shared__ float Bs[33][64];

    int row0 = blockIdx.x * 128;
    int b  = row0 / NN;
    int n0 = row0 - b*NN;
    int tid = threadIdx.x;
    int tx = tid & 7, ty = tid >> 3;     // 8 col-groups x 32 row-groups

    float acc[4][8];
    #pragma unroll
    for (int i = 0; i < 4; i++)
        #pragma unroll
        for (int j = 0; j < 8; j++) acc[i][j] = 0.f;

    for (int m = 0; m < NMAT; m++) {
        const float* Xm = g_X + (size_t)(5+m)*NN*CC;
        for (int k0 = 0; k0 < FF; k0 += 33) {
            for (int idx = tid; idx < 128*33; idx += 256) {
                int rr = idx / 33, fl = idx - rr*33;
                As[fl][rr] = Xm[(size_t)(n0+rr)*CC + b*FF + k0 + fl];
            }
            for (int idx = tid; idx < 33*64; idx += 256) {
                int fl = idx >> 6, o = idx & 63;
                Bs[fl][o] = Wc[((k0+fl)*NMAT + m)*HH + o];
            }
            __syncthreads();
            #pragma unroll 3
            for (int kk = 0; kk < 33; kk++) {
                float a[4], bv[8];
                *(float4*)&a[0]  = *(const float4*)&As[kk][ty*4];
                *(float4*)&bv[0] = *(const float4*)&Bs[kk][tx*8];
                *(float4*)&bv[4] = *(const float4*)&Bs[kk][tx*8+4];
                #pragma unroll
                for (int i = 0; i < 4; i++)
                    #pragma unroll
                    for (int j = 0; j < 8; j++)
                        acc[i][j] += a[i]*bv[j];
            }
            __syncthreads();
        }
    }

    #pragma unroll
    for (int i = 0; i < 4; i++) {
        int rr = ty*4 + i;
        int n  = n0 + rr;
        int row = row0 + rr;
        #pragma unroll
        for (int j = 0; j < 8; j++) {
            int o = tx*8 + j;
            float c = tanhf(acc[i][j] + bc[o]);
            size_t sidx = (size_t)b*NN*HH + (size_t)n*HH + o;
            float u  = g_U[(size_t)row*HH + o];
            float st = state[sidx];
            float ns = u*st + (1.f - u)*c;
            out[sidx] = ns;
            if (dup) out[sidx + (size_t)BB*NN*HH] = ns;
        }
    }
}

// ---------------- launch ------------------------------------------------------
extern "C" void kernel_launch(void* const* d_in, const int* in_sizes, int n_in,
                              void* d_out, int out_size)
{
    const float* inputs = (const float*)d_in[0];
    const float* state  = (const float*)d_in[1];
    const int*   esrc   = (const int*)  d_in[2];
    const int*   edst   = (const int*)  d_in[3];
    const float* v1     = (const float*)d_in[4];
    const float* v2     = (const float*)d_in[5];
    const float* Wg     = (const float*)d_in[6];
    const float* bg     = (const float*)d_in[7];
    const float* Wc     = (const float*)d_in[8];
    const float* bc     = (const float*)d_in[9];
    float* out = (float*)d_out;
    int dup = (out_size >= 2*BB*NN*HH) ? 1 : 0;

    k_zero<<<NN/256, 256>>>();
    k_count<<<EE/256, 256>>>(esrc, edst);
    k_scan<<<1, 1024>>>();
    k_scatter<<<EE/256, 256>>>(esrc, edst);
    k_sortfill<<<NN/256, 256>>>(esrc, edst, v1, v2);

    k_build_x0<<<(NN*CC)/256, 256>>>(inputs, state);

    // gate diffusion: X1 = A1 X0 ; X2 = 2 A1 X1 - X0 ; X3 = A2 X0 ; X4 = 2 A2 X3 - X0
    k_spmm<<<NN, 256>>>(0, 0, 1, -1, 1.f,  0.f);
    k_spmm<<<NN, 256>>>(0, 1, 2,  0, 2.f, -1.f);
    k_spmm<<<NN, 256>>>(1, 0, 3, -1, 1.f,  0.f);
    k_spmm<<<NN, 256>>>(1, 3, 4,  0, 2.f, -1.f);

    k_gemm_gate<<<(BB*NN)/128, 256>>>(Wg, bg, state);

    // candidate diffusion on Xc0 = concat(inputs, r*state)
    k_spmm<<<NN, 256>>>(0, 5, 6, -1, 1.f,  0.f);
    k_spmm<<<NN, 256>>>(0, 6, 7,  5, 2.f, -1.f);
    k_spmm<<<NN, 256>>>(1, 5, 8, -1, 1.f,  0.f);
    k_spmm<<<NN, 256>>>(1, 8, 9,  5, 2.f, -1.f);

    k_gemm_cand<<<(BB*NN)/128, 256>>>(Wc, bc, state, out, dup);
}

// round 2
// speedup vs baseline: 1.5800x; 1.5800x over previous
#include <cuda_runtime.h>
#include <cuda_fp16.h>
#include <math.h>

#define NN   8192
#define BB   16
#define IND  2
#define HH   64
#define FF   66            // IN_DIM + HID
#define CC   (FF*BB)       // 1056 halves per node row
#define CCV  (CC/4)        // 264 uint2 (4 halves) per node row
#define EE   131072
#define NMAT 5
#define KP   72            // padded K per diffusion matrix (66 -> 72)

// ---------------- device scratch (static: no allocation allowed) ------------
__device__ __half g_X[(size_t)10*NN*CC];         // 10 diffusion buffers (0..4 gate, 5..9 cand)
__device__ float  g_U[(size_t)BB*NN*HH];         // update gate u
__device__ __half g_Wg_h[NMAT*128*FF];           // W_gate transposed: [m][o][f]
__device__ __half g_Wc_h[NMAT*64*FF];            // W_cand transposed: [m][o][f]
__device__ int   g_cnt[2][NN];
__device__ int   g_cur[2][NN];
__device__ int   g_ptr[2][NN+1];
__device__ int   g_eidx[2][EE];
__device__ int   g_ccol[2][EE];
__device__ float g_cval[2][EE];

// ---------------- CSR build (deterministic) ---------------------------------
__global__ void k_zero()
{
    int i = blockIdx.x*blockDim.x + threadIdx.x;
    if (i < NN) { g_cnt[0][i]=0; g_cnt[1][i]=0; g_cur[0][i]=0; g_cur[1][i]=0; }
}

__global__ void k_count(const int* __restrict__ src, const int* __restrict__ dst)
{
    int e = blockIdx.x*blockDim.x + threadIdx.x;
    if (e < EE) {
        atomicAdd(&g_cnt[0][src[e]], 1);
        atomicAdd(&g_cnt[1][dst[e]], 1);
    }
}

__global__ void k_scan()   // 1 block, 1024 threads, both matrices
{
    __shared__ int s[1024];
    int tid = threadIdx.x;
    for (int m = 0; m < 2; m++) {
        int base = tid*8;
        int c[8];
        int s_local = 0;
        #pragma unroll
        for (int j = 0; j < 8; j++) { c[j] = g_cnt[m][base+j]; s_local += c[j]; }
        s[tid] = s_local;
        __syncthreads();
        for (int off = 1; off < 1024; off <<= 1) {
            int v = (tid >= off) ? s[tid-off] : 0;
            __syncthreads();
            s[tid] += v;
            __syncthreads();
        }
        int run = s[tid] - s_local;   // exclusive prefix
        #pragma unroll
        for (int j = 0; j < 8; j++) { g_ptr[m][base+j] = run; run += c[j]; }
        if (tid == 1023) g_ptr[m][NN] = run;
        __syncthreads();
    }
}

__global__ void k_scatter(const int* __restrict__ src, const int* __restrict__ dst)
{
    int e = blockIdx.x*blockDim.x + threadIdx.x;
    if (e < EE) {
        int r = src[e];
        int p = g_ptr[0][r] + atomicAdd(&g_cur[0][r], 1);
        g_eidx[0][p] = e;
        r = dst[e];
        p = g_ptr[1][r] + atomicAdd(&g_cur[1][r], 1);
        g_eidx[1][p] = e;
    }
}

__global__ void k_sortfill(const int* __restrict__ src, const int* __restrict__ dst,
                           const float* __restrict__ v1, const float* __restrict__ v2)
{
    int r = blockIdx.x*blockDim.x + threadIdx.x;
    if (r >= NN) return;
    for (int m = 0; m < 2; m++) {
        int beg = g_ptr[m][r], end = g_ptr[m][r+1];
        for (int i = beg+1; i < end; i++) {
            int key = g_eidx[m][i];
            int j = i-1;
            while (j >= beg && g_eidx[m][j] > key) { g_eidx[m][j+1] = g_eidx[m][j]; j--; }
            g_eidx[m][j+1] = key;
        }
        for (int i = beg; i < end; i++) {
            int e = g_eidx[m][i];
            if (m == 0) { g_ccol[0][i] = dst[e]; g_cval[0][i] = v1[e]; }
            else        { g_ccol[1][i] = src[e]; g_cval[1][i] = v2[e]; }
        }
    }
}

// ---------------- weight prep: fp32 -> fp16, transpose to [m][o][f] ----------
__global__ void k_prep_w(const float* __restrict__ Wg, const float* __restrict__ Wc)
{
    int i = blockIdx.x*blockDim.x + threadIdx.x;
    int ng = NMAT*128*FF;
    int nc = NMAT*64*FF;
    if (i < ng) {
        int m = i / (128*FF);
        int rem = i - m*(128*FF);
        int o = rem / FF, f = rem - o*FF;
        g_Wg_h[i] = __float2half_rn(Wg[(f*NMAT + m)*128 + o]);
    } else if (i < ng + nc) {
        int j = i - ng;
        int m = j / (64*FF);
        int rem = j - m*(64*FF);
        int o = rem / FF, f = rem - o*FF;
        g_Wc_h[j] = __float2half_rn(Wc[(f*NMAT + m)*64 + o]);
    }
}

// ---------------- build x0 (fp16) --------------------------------------------
__global__ void k_build_x0(const float* __restrict__ inputs, const float* __restrict__ state)
{
    size_t idx = (size_t)blockIdx.x*blockDim.x + threadIdx.x;   // covers NN*CC exactly
    int n = (int)(idx / CC);
    int c = (int)(idx - (size_t)n*CC);
    int b = c / FF, f = c - b*FF;
    float v = (f < IND) ? inputs[(size_t)b*NN*IND + (size_t)n*IND + f]
                        : state [(size_t)b*NN*HH  + (size_t)n*HH  + (f-IND)];
    __half h = __float2half_rn(v);
    g_X[idx] = h;
    if (f < IND) g_X[(size_t)5*NN*CC + idx] = h;
}

// ---------------- SPMM (fp16 data, fp32 accumulate) ---------------------------
// Runs two independent spmms via blockIdx.y:  Y = alpha * A_m X  + beta * Z
__global__ void __launch_bounds__(256) k_spmm2(int m0,int xi0,int yi0,
                                               int m1,int xi1,int yi1,
                                               int zi, float alpha, float beta)
{
    int which = blockIdx.y;
    int m  = which ? m1  : m0;
    int xi = which ? xi1 : xi0;
    int yi = which ? yi1 : yi0;

    const uint2* __restrict__ X = (const uint2*)(g_X + (size_t)xi*NN*CC);
    uint2*       __restrict__ Y = (uint2*)      (g_X + (size_t)yi*NN*CC);
    const uint2* Z = (zi >= 0) ? (const uint2*)(g_X + (size_t)zi*NN*CC) : nullptr;

    int r   = blockIdx.x;
    int beg = g_ptr[m][r], end = g_ptr[m][r+1];
    int tid = threadIdx.x;

    __shared__ int   scol[64];
    __shared__ float sval[64];

    float4 acc0 = make_float4(0.f,0.f,0.f,0.f);
    float4 acc1 = make_float4(0.f,0.f,0.f,0.f);

    for (int cb = beg; cb < end; cb += 64) {
        int cnt = min(64, end - cb);
        if (tid < cnt) { scol[tid] = g_ccol[m][cb+tid]; sval[tid] = g_cval[m][cb+tid]; }
        __syncthreads();
        for (int j = 0; j < cnt; j++) {
            size_t base = (size_t)scol[j]*CCV;
            float w = sval[j];
            uint2 h = X[base + tid];
            float2 p0 = __half22float2(*(const __half2*)&h.x);
            float2 p1 = __half22float2(*(const __half2*)&h.y);
            acc0.x += w*p0.x; acc0.y += w*p0.y; acc0.z += w*p1.x; acc0.w += w*p1.y;
            if (tid < CCV-256) {
                uint2 h2 = X[base + 256 + tid];
                float2 q0 = __half22float2(*(const __half2*)&h2.x);
                float2 q1 = __half22float2(*(const __half2*)&h2.y);
                acc1.x += w*q0.x; acc1.y += w*q0.y; acc1.z += w*q1.x; acc1.w += w*q1.y;
            }
        }
        __syncthreads();
    }

    size_t yb = (size_t)r*CCV;
    float4 o;
    o.x = alpha*acc0.x; o.y = alpha*acc0.y; o.z = alpha*acc0.z; o.w = alpha*acc0.w;
    if (Z) {
        uint2 zh = Z[yb+tid];
        float2 z0 = __half22float2(*(const __half2*)&zh.x);
        float2 z1 = __half22float2(*(const __half2*)&zh.y);
        o.x += beta*z0.x; o.y += beta*z0.y; o.z += beta*z1.x; o.w += beta*z1.y;
    }
    {
        __half2 lo = __floats2half2_rn(o.x, o.y);
        __half2 hi = __floats2half2_rn(o.z, o.w);
        uint2 st; st.x = *(unsigned int*)&lo; st.y = *(unsigned int*)&hi;
        Y[yb + tid] = st;
    }
    if (tid < CCV-256) {
        o.x = alpha*acc1.x; o.y = alpha*acc1.y; o.z = alpha*acc1.z; o.w = alpha*acc1.w;
        if (Z) {
            uint2 zh = Z[yb+256+tid];
            float2 z0 = __half22float2(*(const __half2*)&zh.x);
            float2 z1 = __half22float2(*(const __half2*)&zh.y);
            o.x += beta*z0.x; o.y += beta*z0.y; o.z += beta*z1.x; o.w += beta*z1.y;
        }
        __half2 lo = __floats2half2_rn(o.x, o.y);
        __half2 hi = __floats2half2_rn(o.z, o.w);
        uint2 st; st.x = *(unsigned int*)&lo; st.y = *(unsigned int*)&hi;
        Y[yb + 256 + tid] = st;
    }
}

// ---------------- HMMA helpers -----------------------------------------------
__device__ __forceinline__ void mma_16816(float c[4], const unsigned a[4], const unsigned b[2]) {
    asm volatile(
        "mma.sync.aligned.m16n8k16.row.col.f32.f16.f16.f32 "
        "{%0,%1,%2,%3},{%4,%5,%6,%7},{%8,%9},{%0,%1,%2,%3};\n"
        : "+f"(c[0]), "+f"(c[1]), "+f"(c[2]), "+f"(c[3])
        : "r"(a[0]), "r"(a[1]), "r"(a[2]), "r"(a[3]), "r"(b[0]), "r"(b[1]));
}
__device__ __forceinline__ void mma_1688(float c[4], const unsigned a[2], const unsigned b0) {
    asm volatile(
        "mma.sync.aligned.m16n8k8.row.col.f32.f16.f16.f32 "
        "{%0,%1,%2,%3},{%4,%5},{%6},{%0,%1,%2,%3};\n"
        : "+f"(c[0]), "+f"(c[1]), "+f"(c[2]), "+f"(c[3])
        : "r"(a[0]), "r"(a[1]), "r"(b0));
}

// ---------------- gate GEMM (tensor core) + fused gating ----------------------
// M=B*N, N=128, K=5*66. Block: 128 rows x 128 cols, 8 warps (4x2).
__global__ void __launch_bounds__(256) k_gemm_gate(const float* __restrict__ bg,
                                                   const float* __restrict__ state)
{
    __shared__ __half As[128][KP];
    __shared__ __half Bs[128][KP];

    int row0 = blockIdx.x * 128;
    int b  = row0 / NN;
    int n0 = row0 - b*NN;
    int tid = threadIdx.x;
    int wid = tid >> 5, lane = tid & 31;
    int q = lane & 3, rr_ = lane >> 2;
    int warp_m = wid & 3, warp_n = wid >> 2;

    float acc[2][8][4];
    #pragma unroll
    for (int i = 0; i < 2; i++)
        #pragma unroll
        for (int j = 0; j < 8; j++)
            #pragma unroll
            for (int k = 0; k < 4; k++) acc[i][j][k] = 0.f;

    const __half2 zero2 = __floats2half2_rn(0.f, 0.f);

    for (int m = 0; m < NMAT; m++) {
        const __half* Xm = g_X + (size_t)m*NN*CC;
        const __half* Wm = g_Wg_h + m*128*FF;
        __syncthreads();
        // As[rr][0..71]: 33 data half2 + 3 zero half2 per row
        for (int idx = tid; idx < 128*36; idx += 256) {
            int rrow = idx / 36, j = idx - rrow*36;
            __half2 v = (j < 33) ? *(const __half2*)(Xm + (size_t)(n0+rrow)*CC + b*FF + 2*j) : zero2;
            *(__half2*)&As[rrow][2*j] = v;
        }
        for (int idx = tid; idx < 128*36; idx += 256) {
            int o = idx / 36, j = idx - o*36;
            __half2 v = (j < 33) ? *(const __half2*)(Wm + o*FF + 2*j) : zero2;
            *(__half2*)&Bs[o][2*j] = v;
        }
        __syncthreads();

        #pragma unroll
        for (int ks = 0; ks < 4; ks++) {
            int k0 = ks*16;
            unsigned af[2][4];
            #pragma unroll
            for (int mt = 0; mt < 2; mt++) {
                int row = warp_m*32 + mt*16 + rr_;
                af[mt][0] = *(const unsigned*)&As[row  ][k0 + 2*q];
                af[mt][1] = *(const unsigned*)&As[row+8][k0 + 2*q];
                af[mt][2] = *(const unsigned*)&As[row  ][k0 + 8 + 2*q];
                af[mt][3] = *(const unsigned*)&As[row+8][k0 + 8 + 2*q];
            }
            #pragma unroll
            for (int nt = 0; nt < 8; nt++) {
                int o = warp_n*64 + nt*8 + rr_;
                unsigned bf[2];
                bf[0] = *(const unsigned*)&Bs[o][k0 + 2*q];
                bf[1] = *(const unsigned*)&Bs[o][k0 + 8 + 2*q];
                mma_16816(acc[0][nt], af[0], bf);
                mma_16816(acc[1][nt], af[1], bf);
            }
        }
        { // k8 tail: k = 64..71
            unsigned af[2][2];
            #pragma unroll
            for (int mt = 0; mt < 2; mt++) {
                int row = warp_m*32 + mt*16 + rr_;
                af[mt][0] = *(const unsigned*)&As[row  ][64 + 2*q];
                af[mt][1] = *(const unsigned*)&As[row+8][64 + 2*q];
            }
            #pragma unroll
            for (int nt = 0; nt < 8; nt++) {
                int o = warp_n*64 + nt*8 + rr_;
                unsigned b0 = *(const unsigned*)&Bs[o][64 + 2*q];
                mma_1688(acc[0][nt], af[0], b0);
                mma_1688(acc[1][nt], af[1], b0);
            }
        }
    }

    __half* gX5 = g_X + (size_t)5*NN*CC;
    #pragma unroll
    for (int mt = 0; mt < 2; mt++) {
        #pragma unroll
        for (int nt = 0; nt < 8; nt++) {
            #pragma unroll
            for (int ci = 0; ci < 4; ci++) {
                int row_l = warp_m*32 + mt*16 + rr_ + ((ci >> 1) ? 8 : 0);
                int col   = warp_n*64 + nt*8 + 2*q + (ci & 1);
                int n = n0 + row_l;
                float z = acc[mt][nt][ci] + bg[col];
                float s = 1.f/(1.f + expf(-z));
                if (col < HH) {
                    float rs = s * state[(size_t)b*NN*HH + (size_t)n*HH + col];
                    gX5[(size_t)n*CC + b*FF + IND + col] = __float2half_rn(rs);
                } else {
                    g_U[(size_t)(row0+row_l)*HH + (col-HH)] = s;
                }
            }
        }
    }
}

// ---------------- candidate GEMM (tensor core) + GRU combine ------------------
// M=B*N, N=64. Block: 128 rows x 64 cols, 8 warps (4x2, 32 cols per warp_n).
__global__ void __launch_bounds__(256) k_gemm_cand(const float* __restrict__ bc,
                                                   const float* __restrict__ state,
                                                   float* __restrict__ out, int dup)
{
    __shared__ __half As[128][KP];
    __shared__ __half Bs[64][KP];

    int row0 = blockIdx.x * 128;
    int b  = row0 / NN;
    int n0 = row0 - b*NN;
    int tid = threadIdx.x;
    int wid = tid >> 5, lane = tid & 31;
    int q = lane & 3, rr_ = lane >> 2;
    int warp_m = wid & 3, warp_n = wid >> 2;

    float acc[2][4][4];
    #pragma unroll
    for (int i = 0; i < 2; i++)
        #pragma unroll
        for (int j = 0; j < 4; j++)
            #pragma unroll
            for (int k = 0; k < 4; k++) acc[i][j][k] = 0.f;

    const __half2 zero2 = __floats2half2_rn(0.f, 0.f);

    for (int m = 0; m < NMAT; m++) {
        const __half* Xm = g_X + (size_t)(5+m)*NN*CC;
        const __half* Wm = g_Wc_h + m*64*FF;
        __syncthreads();
        for (int idx = tid; idx < 128*36; idx += 256) {
            int rrow = idx / 36, j = idx - rrow*36;
            __half2 v = (j < 33) ? *(const __half2*)(Xm + (size_t)(n0+rrow)*CC + b*FF + 2*j) : zero2;
            *(__half2*)&As[rrow][2*j] = v;
        }
        for (int idx = tid; idx < 64*36; idx += 256) {
            int o = idx / 36, j = idx - o*36;
            __half2 v = (j < 33) ? *(const __half2*)(Wm + o*FF + 2*j) : zero2;
            *(__half2*)&Bs[o][2*j] = v;
        }
        __syncthreads();

        #pragma unroll
        for (int ks = 0; ks < 4; ks++) {
            int k0 = ks*16;
            unsigned af[2][4];
            #pragma unroll
            for (int mt = 0; mt < 2; mt++) {
                int row = warp_m*32 + mt*16 + rr_;
                af[mt][0] = *(const unsigned*)&As[row  ][k0 + 2*q];
                af[mt][1] = *(const unsigned*)&As[row+8][k0 + 2*q];
                af[mt][2] = *(const unsigned*)&As[row  ][k0 + 8 + 2*q];
                af[mt][3] = *(const unsigned*)&As[row+8][k0 + 8 + 2*q];
            }
            #pragma unroll
            for (int nt = 0; nt < 4; nt++) {
                int o = warp_n*32 + nt*8 + rr_;
                unsigned bf[2];
                bf[0] = *(const unsigned*)&Bs[o][k0 + 2*q];
                bf[1] = *(const unsigned*)&Bs[o][k0 + 8 + 2*q];
                mma_16816(acc[0][nt], af[0], bf);
                mma_16816(acc[1][nt], af[1], bf);
            }
        }
        {
            unsigned af[2][2];
            #pragma unroll
            for (int mt = 0; mt < 2; mt++) {
                int row = warp_m*32 + mt*16 + rr_;
                af[mt][0] = *(const unsigned*)&As[row  ][64 + 2*q];
                af[mt][1] = *(const unsigned*)&As[row+8][64 + 2*q];
            }
            #pragma unroll
            for (int nt = 0; nt < 4; nt++) {
                int o = warp_n*32 + nt*8 + rr_;
                unsigned b0 = *(const unsigned*)&Bs[o][64 + 2*q];
                mma_1688(acc[0][nt], af[0], b0);
                mma_1688(acc[1][nt], af[1], b0);
            }
        }
    }

    #pragma unroll
    for (int mt = 0; mt < 2; mt++) {
        #pragma unroll
        for (int nt = 0; nt < 4; nt++) {
            #pragma unroll
            for (int ci = 0; ci < 4; ci++) {
                int row_l = warp_m*32 + mt*16 + rr_ + ((ci >> 1) ? 8 : 0);
                int col   = warp_n*32 + nt*8 + 2*q + (ci & 1);
                int n = n0 + row_l;
                int row = row0 + row_l;
                float c = tanhf(acc[mt][nt][ci] + bc[col]);
                size_t sidx = (size_t)b*NN*HH + (size_t)n*HH + col;
                float u  = g_U[(size_t)row*HH + col];
                float st = state[sidx];
                float ns = u*st + (1.f - u)*c;
                out[sidx] = ns;
                if (dup) out[sidx + (size_t)BB*NN*HH] = ns;
            }
        }
    }
}

// ---------------- launch ------------------------------------------------------
extern "C" void kernel_launch(void* const* d_in, const int* in_sizes, int n_in,
                              void* d_out, int out_size)
{
    const float* inputs = (const float*)d_in[0];
    const float* state  = (const float*)d_in[1];
    const int*   esrc   = (const int*)  d_in[2];
    const int*   edst   = (const int*)  d_in[3];
    const float* v1     = (const float*)d_in[4];
    const float* v2     = (const float*)d_in[5];
    const float* Wg     = (const float*)d_in[6];
    const float* bg     = (const float*)d_in[7];
    const float* Wc     = (const float*)d_in[8];
    const float* bc     = (const float*)d_in[9];
    float* out = (float*)d_out;
    int dup = (out_size >= 2*BB*NN*HH) ? 1 : 0;

    k_zero<<<NN/256, 256>>>();
    k_count<<<EE/256, 256>>>(esrc, edst);
    k_scan<<<1, 1024>>>();
    k_scatter<<<EE/256, 256>>>(esrc, edst);
    k_sortfill<<<NN/256, 256>>>(esrc, edst, v1, v2);

    k_prep_w<<<(NMAT*128*FF + NMAT*64*FF + 255)/256, 256>>>(Wg, Wc);
    k_build_x0<<<(NN*CC)/256, 256>>>(inputs, state);

    // gate diffusion: X1 = A1 X0 ; X3 = A2 X0 ; then X2 = 2 A1 X1 - X0 ; X4 = 2 A2 X3 - X0
    k_spmm2<<<dim3(NN,2), 256>>>(0,0,1,  1,0,3,  -1, 1.f,  0.f);
    k_spmm2<<<dim3(NN,2), 256>>>(0,1,2,  1,3,4,   0, 2.f, -1.f);

    k_gemm_gate<<<(BB*NN)/128, 256>>>(bg, state);

    // candidate diffusion on Xc0 = concat(inputs, r*state) (buffer 5)
    k_spmm2<<<dim3(NN,2), 256>>>(0,5,6,  1,5,8,  -1, 1.f,  0.f);
    k_spmm2<<<dim3(NN,2), 256>>>(0,6,7,  1,8,9,   5, 2.f, -1.f);

    k_gemm_cand<<<(BB*NN)/128, 256>>>(bc, state, out, dup);
}

// round 3
// speedup vs baseline: 2.0283x; 1.2837x over previous
#include <cuda_runtime.h>
#include <cuda_fp16.h>
#include <math.h>

#define NN   8192
#define BB   16
#define IND  2
#define HH   64
#define FF   66            // IN_DIM + HID
#define CH   72            // padded halves per (n,b) segment (16B aligned)
#define CROW (BB*CH)       // 1152 halves per node row = 2304 B
#define NV4  (CROW/8)      // 144 uint4 per node row
#define EE   131072
#define NMAT 5
#define KP   72

// ---------------- device scratch (static: no allocation allowed) ------------
__device__ __half g_X[(size_t)10*NN*CROW];       // 10 diffusion buffers (0..4 gate, 5..9 cand)
__device__ float  g_U[(size_t)BB*NN*HH];         // update gate u
__device__ __half g_Wg_h[NMAT*128*CH];           // W_gate: [m][o][f padded 72]
__device__ __half g_Wc_h[NMAT*64*CH];            // W_cand: [m][o][f padded 72]
__device__ int   g_cnt[2][NN];
__device__ int   g_cur[2][NN];
__device__ int   g_ptr[2][NN+1];
__device__ int   g_eidx[2][EE];
__device__ int2  g_cw[2][EE];                    // .x = col, .y = float bits of val

// ---------------- CSR build (deterministic) ---------------------------------
__global__ void k_zero()
{
    int i = blockIdx.x*blockDim.x + threadIdx.x;
    if (i < NN) { g_cnt[0][i]=0; g_cnt[1][i]=0; g_cur[0][i]=0; g_cur[1][i]=0; }
}

__global__ void k_count(const int* __restrict__ src, const int* __restrict__ dst)
{
    int e = blockIdx.x*blockDim.x + threadIdx.x;
    if (e < EE) {
        atomicAdd(&g_cnt[0][src[e]], 1);
        atomicAdd(&g_cnt[1][dst[e]], 1);
    }
}

__global__ void k_scan()   // 1 block, 1024 threads, both matrices
{
    __shared__ int s[1024];
    int tid = threadIdx.x;
    for (int m = 0; m < 2; m++) {
        int base = tid*8;
        int c[8];
        int s_local = 0;
        #pragma unroll
        for (int j = 0; j < 8; j++) { c[j] = g_cnt[m][base+j]; s_local += c[j]; }
        s[tid] = s_local;
        __syncthreads();
        for (int off = 1; off < 1024; off <<= 1) {
            int v = (tid >= off) ? s[tid-off] : 0;
            __syncthreads();
            s[tid] += v;
            __syncthreads();
        }
        int run = s[tid] - s_local;
        #pragma unroll
        for (int j = 0; j < 8; j++) { g_ptr[m][base+j] = run; run += c[j]; }
        if (tid == 1023) g_ptr[m][NN] = run;
        __syncthreads();
    }
}

__global__ void k_scatter(const int* __restrict__ src, const int* __restrict__ dst)
{
    int e = blockIdx.x*blockDim.x + threadIdx.x;
    if (e < EE) {
        int r = src[e];
        int p = g_ptr[0][r] + atomicAdd(&g_cur[0][r], 1);
        g_eidx[0][p] = e;
        r = dst[e];
        p = g_ptr[1][r] + atomicAdd(&g_cur[1][r], 1);
        g_eidx[1][p] = e;
    }
}

__global__ void k_sortfill(const int* __restrict__ src, const int* __restrict__ dst,
                           const float* __restrict__ v1, const float* __restrict__ v2)
{
    int r = blockIdx.x*blockDim.x + threadIdx.x;
    if (r >= NN) return;
    for (int m = 0; m < 2; m++) {
        int beg = g_ptr[m][r], end = g_ptr[m][r+1];
        for (int i = beg+1; i < end; i++) {
            int key = g_eidx[m][i];
            int j = i-1;
            while (j >= beg && g_eidx[m][j] > key) { g_eidx[m][j+1] = g_eidx[m][j]; j--; }
            g_eidx[m][j+1] = key;
        }
        for (int i = beg; i < end; i++) {
            int e = g_eidx[m][i];
            int2 cw;
            if (m == 0) { cw.x = dst[e]; cw.y = __float_as_int(v1[e]); }
            else        { cw.x = src[e]; cw.y = __float_as_int(v2[e]); }
            g_cw[m][i] = cw;
        }
    }
}

// ---------------- fused init: build x0 + weight convert ----------------------
__global__ void k_init(const float* __restrict__ inputs, const float* __restrict__ state,
                       const float* __restrict__ Wg, const float* __restrict__ Wc)
{
    const size_t T1 = (size_t)NN*CROW;
    const size_t T2 = (size_t)NMAT*128*CH;
    size_t idx = (size_t)blockIdx.x*blockDim.x + threadIdx.x;
    if (idx < T1) {
        int n = (int)(idx / CROW);
        int c = (int)(idx - (size_t)n*CROW);
        int b = c / CH, f = c - b*CH;
        float v = 0.f;
        if (f < IND)      v = inputs[(size_t)b*NN*IND + (size_t)n*IND + f];
        else if (f < FF)  v = state [(size_t)b*NN*HH  + (size_t)n*HH  + (f-IND)];
        __half h = __float2half_rn(v);
        g_X[idx] = h;
        g_X[(size_t)5*NN*CROW + idx] = (f < IND) ? h : __half(0.f);
    } else if (idx < T1 + T2) {
        size_t i2 = idx - T1;
        int m = (int)(i2 / (128*CH));
        int rem = (int)(i2 - (size_t)m*(128*CH));
        int o = rem / CH, f = rem - o*CH;
        g_Wg_h[i2] = (f < FF) ? __float2half_rn(Wg[(f*NMAT + m)*128 + o]) : __half(0.f);
    } else if (idx < T1 + T2 + (size_t)NMAT*64*CH) {
        size_t i3 = idx - T1 - T2;
        int m = (int)(i3 / (64*CH));
        int rem = (int)(i3 - (size_t)m*(64*CH));
        int o = rem / CH, f = rem - o*CH;
        g_Wc_h[i3] = (f < FF) ? __float2half_rn(Wc[(f*NMAT + m)*64 + o]) : __half(0.f);
    }
}

// ---------------- SPMM (fp16 data, fp32 acc), 2 rows / 256-thread block ------
// Y = alpha * A_m X + beta * Z ; two independent spmms via blockIdx.y
__global__ void __launch_bounds__(256) k_spmm2(int m0,int xi0,int yi0,
                                               int m1,int xi1,int yi1,
                                               int zi, float alpha, float beta)
{
    int which = blockIdx.y;
    int m  = which ? m1  : m0;
    int xi = which ? xi1 : xi0;
    int yi = which ? yi1 : yi0;

    const uint4* __restrict__ X = (const uint4*)(g_X + (size_t)xi*NN*CROW);
    uint4*       __restrict__ Y = (uint4*)      (g_X + (size_t)yi*NN*CROW);
    const uint4* Z = (zi >= 0) ? (const uint4*)(g_X + (size_t)zi*NN*CROW) : nullptr;

    int sub = threadIdx.x >> 7;          // 0/1: which row of this block
    int t   = threadIdx.x & 127;
    int r   = blockIdx.x*2 + sub;
    int beg = g_ptr[m][r], end = g_ptr[m][r+1];
    const int2* __restrict__ cw = g_cw[m];

    float acc[8]  = {0.f,0.f,0.f,0.f,0.f,0.f,0.f,0.f};
    float accB[8] = {0.f,0.f,0.f,0.f,0.f,0.f,0.f,0.f};

    for (int j = beg; j < end; j++) {
        int2 e = __ldg(&cw[j]);
        float w = __int_as_float(e.y);
        const uint4* rb = X + (size_t)e.x * NV4;
        uint4 h = __ldg(&rb[t]);
        {
            float2 p0 = __half22float2(*(const __half2*)&h.x);
            float2 p1 = __half22float2(*(const __half2*)&h.y);
            float2 p2 = __half22float2(*(const __half2*)&h.z);
            float2 p3 = __half22float2(*(const __half2*)&h.w);
            acc[0] += w*p0.x; acc[1] += w*p0.y; acc[2] += w*p1.x; acc[3] += w*p1.y;
            acc[4] += w*p2.x; acc[5] += w*p2.y; acc[6] += w*p3.x; acc[7] += w*p3.y;
        }
        if (t < NV4-128) {
            uint4 h2 = __ldg(&rb[128+t]);
            float2 p0 = __half22float2(*(const __half2*)&h2.x);
            float2 p1 = __half22float2(*(const __half2*)&h2.y);
            float2 p2 = __half22float2(*(const __half2*)&h2.z);
            float2 p3 = __half22float2(*(const __half2*)&h2.w);
            accB[0] += w*p0.x; accB[1] += w*p0.y; accB[2] += w*p1.x; accB[3] += w*p1.y;
            accB[4] += w*p2.x; accB[5] += w*p2.y; accB[6] += w*p3.x; accB[7] += w*p3.y;
        }
    }

    size_t yb = (size_t)r*NV4;
    {
        float o[8];
        #pragma unroll
        for (int i = 0; i < 8; i++) o[i] = alpha*acc[i];
        if (Z) {
            uint4 zh = Z[yb+t];
            float2 z0 = __half22float2(*(const __half2*)&zh.x);
            float2 z1 = __half22float2(*(const __half2*)&zh.y);
            float2 z2 = __half22float2(*(const __half2*)&zh.z);
            float2 z3 = __half22float2(*(const __half2*)&zh.w);
            o[0]+=beta*z0.x; o[1]+=beta*z0.y; o[2]+=beta*z1.x; o[3]+=beta*z1.y;
            o[4]+=beta*z2.x; o[5]+=beta*z2.y; o[6]+=beta*z3.x; o[7]+=beta*z3.y;
        }
        __half2 a0 = __floats2half2_rn(o[0],o[1]);
        __half2 a1 = __floats2half2_rn(o[2],o[3]);
        __half2 a2 = __floats2half2_rn(o[4],o[5]);
        __half2 a3 = __floats2half2_rn(o[6],o[7]);
        uint4 st; st.x=*(unsigned*)&a0; st.y=*(unsigned*)&a1; st.z=*(unsigned*)&a2; st.w=*(unsigned*)&a3;
        Y[yb + t] = st;
    }
    if (t < NV4-128) {
        float o[8];
        #pragma unroll
        for (int i = 0; i < 8; i++) o[i] = alpha*accB[i];
        if (Z) {
            uint4 zh = Z[yb+128+t];
            float2 z0 = __half22float2(*(const __half2*)&zh.x);
            float2 z1 = __half22float2(*(const __half2*)&zh.y);
            float2 z2 = __half22float2(*(const __half2*)&zh.z);
            float2 z3 = __half22float2(*(const __half2*)&zh.w);
            o[0]+=beta*z0.x; o[1]+=beta*z0.y; o[2]+=beta*z1.x; o[3]+=beta*z1.y;
            o[4]+=beta*z2.x; o[5]+=beta*z2.y; o[6]+=beta*z3.x; o[7]+=beta*z3.y;
        }
        __half2 a0 = __floats2half2_rn(o[0],o[1]);
        __half2 a1 = __floats2half2_rn(o[2],o[3]);
        __half2 a2 = __floats2half2_rn(o[4],o[5]);
        __half2 a3 = __floats2half2_rn(o[6],o[7]);
        uint4 st; st.x=*(unsigned*)&a0; st.y=*(unsigned*)&a1; st.z=*(unsigned*)&a2; st.w=*(unsigned*)&a3;
        Y[yb + 128 + t] = st;
    }
}

// ---------------- HMMA helpers -----------------------------------------------
__device__ __forceinline__ void mma_16816(float c[4], const unsigned a[4], const unsigned b[2]) {
    asm volatile(
        "mma.sync.aligned.m16n8k16.row.col.f32.f16.f16.f32 "
        "{%0,%1,%2,%3},{%4,%5,%6,%7},{%8,%9},{%0,%1,%2,%3};\n"
        : "+f"(c[0]), "+f"(c[1]), "+f"(c[2]), "+f"(c[3])
        : "r"(a[0]), "r"(a[1]), "r"(a[2]), "r"(a[3]), "r"(b[0]), "r"(b[1]));
}
__device__ __forceinline__ void mma_1688(float c[4], const unsigned a[2], const unsigned b0) {
    asm volatile(
        "mma.sync.aligned.m16n8k8.row.col.f32.f16.f16.f32 "
        "{%0,%1,%2,%3},{%4,%5},{%6},{%0,%1,%2,%3};\n"
        : "+f"(c[0]), "+f"(c[1]), "+f"(c[2]), "+f"(c[3])
        : "r"(a[0]), "r"(a[1]), "r"(b0));
}

// ---------------- gate GEMM (tensor core) + fused gating ----------------------
__global__ void __launch_bounds__(256) k_gemm_gate(const float* __restrict__ bg,
                                                   const float* __restrict__ state)
{
    __shared__ __align__(16) __half As[128][KP];
    __shared__ __align__(16) __half Bs[128][KP];

    int row0 = blockIdx.x * 128;
    int b  = row0 / NN;
    int n0 = row0 - b*NN;
    int tid = threadIdx.x;
    int wid = tid >> 5, lane = tid & 31;
    int q = lane & 3, rr_ = lane >> 2;
    int warp_m = wid & 3, warp_n = wid >> 2;

    float acc[2][8][4];
    #pragma unroll
    for (int i = 0; i < 2; i++)
        #pragma unroll
        for (int j = 0; j < 8; j++)
            #pragma unroll
            for (int k = 0; k < 4; k++) acc[i][j][k] = 0.f;

    for (int m = 0; m < NMAT; m++) {
        const __half* Xm = g_X + (size_t)m*NN*CROW;
        const __half* Wm = g_Wg_h + m*128*CH;
        __syncthreads();
        for (int idx = tid; idx < 128*9; idx += 256) {
            int rrow = idx / 9, j = idx - rrow*9;
            ((uint4*)&As[rrow][0])[j] = *(const uint4*)(Xm + (size_t)(n0+rrow)*CROW + b*CH + 8*j);
        }
        for (int idx = tid; idx < 128*9; idx += 256) {
            int o = idx / 9, j = idx - o*9;
            ((uint4*)&Bs[o][0])[j] = *(const uint4*)(Wm + o*CH + 8*j);
        }
        __syncthreads();

        #pragma unroll
        for (int ks = 0; ks < 4; ks++) {
            int k0 = ks*16;
            unsigned af[2][4];
            #pragma unroll
            for (int mt = 0; mt < 2; mt++) {
                int row = warp_m*32 + mt*16 + rr_;
                af[mt][0] = *(const unsigned*)&As[row  ][k0 + 2*q];
                af[mt][1] = *(const unsigned*)&As[row+8][k0 + 2*q];
                af[mt][2] = *(const unsigned*)&As[row  ][k0 + 8 + 2*q];
                af[mt][3] = *(const unsigned*)&As[row+8][k0 + 8 + 2*q];
            }
            #pragma unroll
            for (int nt = 0; nt < 8; nt++) {
                int o = warp_n*64 + nt*8 + rr_;
                unsigned bf[2];
                bf[0] = *(const unsigned*)&Bs[o][k0 + 2*q];
                bf[1] = *(const unsigned*)&Bs[o][k0 + 8 + 2*q];
                mma_16816(acc[0][nt], af[0], bf);
                mma_16816(acc[1][nt], af[1], bf);
            }
        }
        { // k8 tail: k = 64..71 (pads are zero)
            unsigned af[2][2];
            #pragma unroll
            for (int mt = 0; mt < 2; mt++) {
                int row = warp_m*32 + mt*16 + rr_;
                af[mt][0] = *(const unsigned*)&As[row  ][64 + 2*q];
                af[mt][1] = *(const unsigned*)&As[row+8][64 + 2*q];
            }
            #pragma unroll
            for (int nt = 0; nt < 8; nt++) {
                int o = warp_n*64 + nt*8 + rr_;
                unsigned b0 = *(const unsigned*)&Bs[o][64 + 2*q];
                mma_1688(acc[0][nt], af[0], b0);
                mma_1688(acc[1][nt], af[1], b0);
            }
        }
    }

    __half* gX5 = g_X + (size_t)5*NN*CROW;
    #pragma unroll
    for (int mt = 0; mt < 2; mt++) {
        #pragma unroll
        for (int nt = 0; nt < 8; nt++) {
            #pragma unroll
            for (int half_ : {0, 1}) {   // ci pair (0,1) then (2,3)
                int row_l = warp_m*32 + mt*16 + rr_ + (half_ ? 8 : 0);
                int col   = warp_n*64 + nt*8 + 2*q;
                int n = n0 + row_l;
                float z0 = acc[mt][nt][2*half_+0] + bg[col];
                float z1 = acc[mt][nt][2*half_+1] + bg[col+1];
                float s0 = 1.f/(1.f + expf(-z0));
                float s1 = 1.f/(1.f + expf(-z1));
                if (col < HH) {
                    float2 st = *(const float2*)&state[(size_t)b*NN*HH + (size_t)n*HH + col];
                    __half2 rs = __floats2half2_rn(s0*st.x, s1*st.y);
                    *(__half2*)&gX5[(size_t)n*CROW + b*CH + IND + col] = rs;
                } else {
                    float2 u; u.x = s0; u.y = s1;
                    *(float2*)&g_U[(size_t)(row0+row_l)*HH + (col-HH)] = u;
                }
            }
        }
    }
}

// ---------------- candidate GEMM (tensor core) + GRU combine ------------------
__global__ void __launch_bounds__(256) k_gemm_cand(const float* __restrict__ bc,
                                                   const float* __restrict__ state,
                                                   float* __restrict__ out, int dup)
{
    __shared__ __align__(16) __half As[128][KP];
    __shared__ __align__(16) __half Bs[64][KP];

    int row0 = blockIdx.x * 128;
    int b  = row0 / NN;
    int n0 = row0 - b*NN;
    int tid = threadIdx.x;
    int wid = tid >> 5, lane = tid & 31;
    int q = lane & 3, rr_ = lane >> 2;
    int warp_m = wid & 3, warp_n = wid >> 2;

    float acc[2][4][4];
    #pragma unroll
    for (int i = 0; i < 2; i++)
        #pragma unroll
        for (int j = 0; j < 4; j++)
            #pragma unroll
            for (int k = 0; k < 4; k++) acc[i][j][k] = 0.f;

    for (int m = 0; m < NMAT; m++) {
        const __half* Xm = g_X + (size_t)(5+m)*NN*CROW;
        const __half* Wm = g_Wc_h + m*64*CH;
        __syncthreads();
        for (int idx = tid; idx < 128*9; idx += 256) {
            int rrow = idx / 9, j = idx - rrow*9;
            ((uint4*)&As[rrow][0])[j] = *(const uint4*)(Xm + (size_t)(n0+rrow)*CROW + b*CH + 8*j);
        }
        for (int idx = tid; idx < 64*9; idx += 256) {
            int o = idx / 9, j = idx - o*9;
            ((uint4*)&Bs[o][0])[j] = *(const uint4*)(Wm + o*CH + 8*j);
        }
        __syncthreads();

        #pragma unroll
        for (int ks = 0; ks < 4; ks++) {
            int k0 = ks*16;
            unsigned af[2][4];
            #pragma unroll
            for (int mt = 0; mt < 2; mt++) {
                int row = warp_m*32 + mt*16 + rr_;
                af[mt][0] = *(const unsigned*)&As[row  ][k0 + 2*q];
                af[mt][1] = *(const unsigned*)&As[row+8][k0 + 2*q];
                af[mt][2] = *(const unsigned*)&As[row  ][k0 + 8 + 2*q];
                af[mt][3] = *(const unsigned*)&As[row+8][k0 + 8 + 2*q];
            }
            #pragma unroll
            for (int nt = 0; nt < 4; nt++) {
                int o = warp_n*32 + nt*8 + rr_;
                unsigned bf[2];
                bf[0] = *(const unsigned*)&Bs[o][k0 + 2*q];
                bf[1] = *(const unsigned*)&Bs[o][k0 + 8 + 2*q];
                mma_16816(acc[0][nt], af[0], bf);
                mma_16816(acc[1][nt], af[1], bf);
            }
        }
        {
            unsigned af[2][2];
            #pragma unroll
            for (int mt = 0; mt < 2; mt++) {
                int row = warp_m*32 + mt*16 + rr_;
                af[mt][0] = *(const unsigned*)&As[row  ][64 + 2*q];
                af[mt][1] = *(const unsigned*)&As[row+8][64 + 2*q];
            }
            #pragma unroll
            for (int nt = 0; nt < 4; nt++) {
                int o = warp_n*32 + nt*8 + rr_;
                unsigned b0 = *(const unsigned*)&Bs[o][64 + 2*q];
                mma_1688(acc[0][nt], af[0], b0);
                mma_1688(acc[1][nt], af[1], b0);
            }
        }
    }

    #pragma unroll
    for (int mt = 0; mt < 2; mt++) {
        #pragma unroll
        for (int nt = 0; nt < 4; nt++) {
            #pragma unroll
            for (int half_ : {0, 1}) {
                int row_l = warp_m*32 + mt*16 + rr_ + (half_ ? 8 : 0);
                int col   = warp_n*32 + nt*8 + 2*q;
                int n = n0 + row_l;
                int row = row0 + row_l;
                float c0 = tanhf(acc[mt][nt][2*half_+0] + bc[col]);
                float c1 = tanhf(acc[mt][nt][2*half_+1] + bc[col+1]);
                size_t sidx = (size_t)b*NN*HH + (size_t)n*HH + col;
                float2 u  = *(const float2*)&g_U[(size_t)row*HH + col];
                float2 st = *(const float2*)&state[sidx];
                float2 ns;
                ns.x = u.x*st.x + (1.f - u.x)*c0;
                ns.y = u.y*st.y + (1.f - u.y)*c1;
                *(float2*)&out[sidx] = ns;
                if (dup) *(float2*)&out[sidx + (size_t)BB*NN*HH] = ns;
            }
        }
    }
}

// ---------------- launch ------------------------------------------------------
extern "C" void kernel_launch(void* const* d_in, const int* in_sizes, int n_in,
                              void* d_out, int out_size)
{
    const float* inputs = (const float*)d_in[0];
    const float* state  = (const float*)d_in[1];
    const int*   esrc   = (const int*)  d_in[2];
    const int*   edst   = (const int*)  d_in[3];
    const float* v1     = (const float*)d_in[4];
    const float* v2     = (const float*)d_in[5];
    const float* Wg     = (const float*)d_in[6];
    const float* bg     = (const float*)d_in[7];
    const float* Wc     = (const float*)d_in[8];
    const float* bc     = (const float*)d_in[9];
    float* out = (float*)d_out;
    int dup = (out_size >= 2*BB*NN*HH) ? 1 : 0;

    k_zero<<<NN/256, 256>>>();
    k_count<<<EE/256, 256>>>(esrc, edst);
    k_scan<<<1, 1024>>>();
    k_scatter<<<EE/256, 256>>>(esrc, edst);
    k_sortfill<<<NN/256, 256>>>(esrc, edst, v1, v2);

    size_t init_total = (size_t)NN*CROW + (size_t)NMAT*128*CH + (size_t)NMAT*64*CH;
    k_init<<<(unsigned)((init_total + 255)/256), 256>>>(inputs, state, Wg, Wc);

    // gate diffusion: X1 = A1 X0 ; X3 = A2 X0 ; then X2 = 2 A1 X1 - X0 ; X4 = 2 A2 X3 - X0
    k_spmm2<<<dim3(NN/2,2), 256>>>(0,0,1,  1,0,3,  -1, 1.f,  0.f);
    k_spmm2<<<dim3(NN/2,2), 256>>>(0,1,2,  1,3,4,   0, 2.f, -1.f);

    k_gemm_gate<<<(BB*NN)/128, 256>>>(bg, state);

    // candidate diffusion on Xc0 = concat(inputs, r*state) (buffer 5)
    k_spmm2<<<dim3(NN/2,2), 256>>>(0,5,6,  1,5,8,  -1, 1.f,  0.f);
    k_spmm2<<<dim3(NN/2,2), 256>>>(0,6,7,  1,8,9,   5, 2.f, -1.f);

    k_gemm_cand<<<(BB*NN)/128, 256>>>(bc, state, out, dup);
}

// round 4
// speedup vs baseline: 2.0352x; 1.0034x over previous
#include <cuda_runtime.h>
#include <cuda_fp16.h>
#include <math.h>

#define NN   8192
#define BB   16
#define IND  2
#define HH   64
#define FF   66            // IN_DIM + HID
#define CH   72            // padded halves per (n,b) segment (16B aligned)
#define CROW (BB*CH)       // 1152 halves per node row = 2304 B
#define NV4  (CROW/8)      // 144 uint4 per node row
#define EE   131072
#define NMAT 5
#define KP   72

// ---------------- device scratch (static: no allocation allowed) ------------
__device__ __half g_X[(size_t)10*NN*CROW];       // 0..4 gate bufs, 5..9 cand bufs
__device__ float  g_U[(size_t)BB*NN*HH];         // update gate u
__device__ __half g_Wg_h[NMAT*128*CH];           // W_gate folded: [m][o][f padded 72]
__device__ __half g_Wc_h[NMAT*64*CH];            // W_cand folded: [m][o][f padded 72]
__device__ int   g_cnt[2][NN];
__device__ int   g_cur[2][NN];
__device__ int   g_ptr[2][NN+1];
__device__ int   g_eidx[2][EE];
__device__ int2  g_cw[2][EE];                    // .x = col, .y = float bits of val

// ---------------- CSR build (deterministic) ---------------------------------
__global__ void k_zero()
{
    int i = blockIdx.x*blockDim.x + threadIdx.x;
    if (i < NN) { g_cnt[0][i]=0; g_cnt[1][i]=0; g_cur[0][i]=0; g_cur[1][i]=0; }
}

__global__ void k_count(const int* __restrict__ src, const int* __restrict__ dst)
{
    int e = blockIdx.x*blockDim.x + threadIdx.x;
    if (e < EE) {
        atomicAdd(&g_cnt[0][src[e]], 1);
        atomicAdd(&g_cnt[1][dst[e]], 1);
    }
}

__global__ void k_scan()   // 1 block, 1024 threads, both matrices
{
    __shared__ int s[1024];
    int tid = threadIdx.x;
    for (int m = 0; m < 2; m++) {
        int base = tid*8;
        int c[8];
        int s_local = 0;
        #pragma unroll
        for (int j = 0; j < 8; j++) { c[j] = g_cnt[m][base+j]; s_local += c[j]; }
        s[tid] = s_local;
        __syncthreads();
        for (int off = 1; off < 1024; off <<= 1) {
            int v = (tid >= off) ? s[tid-off] : 0;
            __syncthreads();
            s[tid] += v;
            __syncthreads();
        }
        int run = s[tid] - s_local;
        #pragma unroll
        for (int j = 0; j < 8; j++) { g_ptr[m][base+j] = run; run += c[j]; }
        if (tid == 1023) g_ptr[m][NN] = run;
        __syncthreads();
    }
}

__global__ void k_scatter(const int* __restrict__ src, const int* __restrict__ dst)
{
    int e = blockIdx.x*blockDim.x + threadIdx.x;
    if (e < EE) {
        int r = src[e];
        int p = g_ptr[0][r] + atomicAdd(&g_cur[0][r], 1);
        g_eidx[0][p] = e;
        r = dst[e];
        p = g_ptr[1][r] + atomicAdd(&g_cur[1][r], 1);
        g_eidx[1][p] = e;
    }
}

__global__ void k_sortfill(const int* __restrict__ src, const int* __restrict__ dst,
                           const float* __restrict__ v1, const float* __restrict__ v2)
{
    int r = blockIdx.x*blockDim.x + threadIdx.x;
    if (r >= NN) return;
    for (int m = 0; m < 2; m++) {
        int beg = g_ptr[m][r], end = g_ptr[m][r+1];
        for (int i = beg+1; i < end; i++) {
            int key = g_eidx[m][i];
            int j = i-1;
            while (j >= beg && g_eidx[m][j] > key) { g_eidx[m][j+1] = g_eidx[m][j]; j--; }
            g_eidx[m][j+1] = key;
        }
        for (int i = beg; i < end; i++) {
            int e = g_eidx[m][i];
            int2 cw;
            if (m == 0) { cw.x = dst[e]; cw.y = __float_as_int(v1[e]); }
            else        { cw.x = src[e]; cw.y = __float_as_int(v2[e]); }
            g_cw[m][i] = cw;
        }
    }
}

// ---------------- fused init: build x0 + folded weight convert ---------------
// Chebyshev fold: W0' = W0 - W2 - W4 ; W2' = 2*W2 ; W4' = 2*W4 (W1, W3 as-is)
// so stage-2 spmms are plain Y = A X (no -X0, no 2x).
__global__ void k_init(const float* __restrict__ inputs, const float* __restrict__ state,
                       const float* __restrict__ Wg, const float* __restrict__ Wc)
{
    const size_t T1 = (size_t)NN*CROW;
    const size_t T2 = (size_t)NMAT*128*CH;
    size_t idx = (size_t)blockIdx.x*blockDim.x + threadIdx.x;
    if (idx < T1) {
        int n = (int)(idx / CROW);
        int c = (int)(idx - (size_t)n*CROW);
        int b = c / CH, f = c - b*CH;
        float v = 0.f;
        if (f < IND)      v = inputs[(size_t)b*NN*IND + (size_t)n*IND + f];
        else if (f < FF)  v = state [(size_t)b*NN*HH  + (size_t)n*HH  + (f-IND)];
        __half h = __float2half_rn(v);
        g_X[idx] = h;
        g_X[(size_t)5*NN*CROW + idx] = (f < IND) ? h : __half(0.f);
    } else if (idx < T1 + T2) {
        size_t i2 = idx - T1;
        int m = (int)(i2 / (128*CH));
        int rem = (int)(i2 - (size_t)m*(128*CH));
        int o = rem / CH, f = rem - o*CH;
        float w = 0.f;
        if (f < FF) {
            const float* base = Wg + (size_t)(f*NMAT)*128 + o;
            if      (m == 0) w = base[0] - base[2*128] - base[4*128];
            else if (m == 2) w = 2.f*base[2*128];
            else if (m == 4) w = 2.f*base[4*128];
            else             w = base[m*128];
        }
        g_Wg_h[i2] = __float2half_rn(w);
    } else if (idx < T1 + T2 + (size_t)NMAT*64*CH) {
        size_t i3 = idx - T1 - T2;
        int m = (int)(i3 / (64*CH));
        int rem = (int)(i3 - (size_t)m*(64*CH));
        int o = rem / CH, f = rem - o*CH;
        float w = 0.f;
        if (f < FF) {
            const float* base = Wc + (size_t)(f*NMAT)*64 + o;
            if      (m == 0) w = base[0] - base[2*64] - base[4*64];
            else if (m == 2) w = 2.f*base[2*64];
            else if (m == 4) w = 2.f*base[4*64];
            else             w = base[m*64];
        }
        g_Wc_h[i3] = __float2half_rn(w);
    }
}

// ---------------- SPMM: Y = A_m X, fp16 data, fp32 acc, unroll-4 prefetch ----
__device__ __forceinline__ void acc8(float* a, float w, uint4 h)
{
    float2 p0 = __half22float2(*(const __half2*)&h.x);
    float2 p1 = __half22float2(*(const __half2*)&h.y);
    float2 p2 = __half22float2(*(const __half2*)&h.z);
    float2 p3 = __half22float2(*(const __half2*)&h.w);
    a[0] += w*p0.x; a[1] += w*p0.y; a[2] += w*p1.x; a[3] += w*p1.y;
    a[4] += w*p2.x; a[5] += w*p2.y; a[6] += w*p3.x; a[7] += w*p3.y;
}

__global__ void __launch_bounds__(256) k_spmm2(int m0,int xi0,int yi0,
                                               int m1,int xi1,int yi1)
{
    int which = blockIdx.y;
    int m  = which ? m1  : m0;
    int xi = which ? xi1 : xi0;
    int yi = which ? yi1 : yi0;

    const uint4* __restrict__ X = (const uint4*)(g_X + (size_t)xi*NN*CROW);
    uint4*       __restrict__ Y = (uint4*)      (g_X + (size_t)yi*NN*CROW);

    int sub = threadIdx.x >> 7;
    int t   = threadIdx.x & 127;
    int r   = blockIdx.x*2 + sub;
    int beg = g_ptr[m][r], end = g_ptr[m][r+1];
    const int2* __restrict__ cw = g_cw[m];

    float acc[8]  = {0.f,0.f,0.f,0.f,0.f,0.f,0.f,0.f};
    float accB[8] = {0.f,0.f,0.f,0.f,0.f,0.f,0.f,0.f};
    const bool tl = (t < NV4-128);

    int j = beg;
    for (; j + 4 <= end; j += 4) {
        int2 e0 = __ldg(cw+j), e1 = __ldg(cw+j+1), e2 = __ldg(cw+j+2), e3 = __ldg(cw+j+3);
        const uint4* r0 = X + (size_t)e0.x*NV4;
        const uint4* r1 = X + (size_t)e1.x*NV4;
        const uint4* r2 = X + (size_t)e2.x*NV4;
        const uint4* r3 = X + (size_t)e3.x*NV4;
        uint4 h0 = __ldg(r0+t), h1 = __ldg(r1+t), h2 = __ldg(r2+t), h3 = __ldg(r3+t);
        uint4 g0, g1, g2, g3;
        if (tl) { g0 = __ldg(r0+128+t); g1 = __ldg(r1+128+t);
                  g2 = __ldg(r2+128+t); g3 = __ldg(r3+128+t); }
        float w0 = __int_as_float(e0.y), w1 = __int_as_float(e1.y);
        float w2 = __int_as_float(e2.y), w3 = __int_as_float(e3.y);
        acc8(acc, w0, h0); acc8(acc, w1, h1); acc8(acc, w2, h2); acc8(acc, w3, h3);
        if (tl) { acc8(accB, w0, g0); acc8(accB, w1, g1);
                  acc8(accB, w2, g2); acc8(accB, w3, g3); }
    }
    for (; j < end; j++) {
        int2 e = __ldg(cw+j);
        float w = __int_as_float(e.y);
        const uint4* rb = X + (size_t)e.x*NV4;
        uint4 h = __ldg(rb+t);
        acc8(acc, w, h);
        if (tl) { uint4 g = __ldg(rb+128+t); acc8(accB, w, g); }
    }

    size_t yb = (size_t)r*NV4;
    {
        __half2 a0 = __floats2half2_rn(acc[0],acc[1]);
        __half2 a1 = __floats2half2_rn(acc[2],acc[3]);
        __half2 a2 = __floats2half2_rn(acc[4],acc[5]);
        __half2 a3 = __floats2half2_rn(acc[6],acc[7]);
        uint4 st; st.x=*(unsigned*)&a0; st.y=*(unsigned*)&a1; st.z=*(unsigned*)&a2; st.w=*(unsigned*)&a3;
        Y[yb + t] = st;
    }
    if (tl) {
        __half2 a0 = __floats2half2_rn(accB[0],accB[1]);
        __half2 a1 = __floats2half2_rn(accB[2],accB[3]);
        __half2 a2 = __floats2half2_rn(accB[4],accB[5]);
        __half2 a3 = __floats2half2_rn(accB[6],accB[7]);
        uint4 st; st.x=*(unsigned*)&a0; st.y=*(unsigned*)&a1; st.z=*(unsigned*)&a2; st.w=*(unsigned*)&a3;
        Y[yb + 128 + t] = st;
    }
}

// ---------------- MMA / ldmatrix helpers --------------------------------------
__device__ __forceinline__ void mma_16816(float c[4], const unsigned a[4], const unsigned b[2]) {
    asm volatile(
        "mma.sync.aligned.m16n8k16.row.col.f32.f16.f16.f32 "
        "{%0,%1,%2,%3},{%4,%5,%6,%7},{%8,%9},{%0,%1,%2,%3};\n"
        : "+f"(c[0]), "+f"(c[1]), "+f"(c[2]), "+f"(c[3])
        : "r"(a[0]), "r"(a[1]), "r"(a[2]), "r"(a[3]), "r"(b[0]), "r"(b[1]));
}
__device__ __forceinline__ void mma_1688(float c[4], const unsigned a[2], const unsigned b0) {
    asm volatile(
        "mma.sync.aligned.m16n8k8.row.col.f32.f16.f16.f32 "
        "{%0,%1,%2,%3},{%4,%5},{%6},{%0,%1,%2,%3};\n"
        : "+f"(c[0]), "+f"(c[1]), "+f"(c[2]), "+f"(c[3])
        : "r"(a[0]), "r"(a[1]), "r"(b0));
}
__device__ __forceinline__ unsigned su32(const void* p) {
    return (unsigned)__cvta_generic_to_shared(p);
}
__device__ __forceinline__ void ldsm4(unsigned* r, unsigned a) {
    asm volatile("ldmatrix.sync.aligned.m8n8.x4.shared.b16 {%0,%1,%2,%3},[%4];"
        : "=r"(r[0]),"=r"(r[1]),"=r"(r[2]),"=r"(r[3]) : "r"(a));
}
__device__ __forceinline__ void ldsm2(unsigned* r, unsigned a) {
    asm volatile("ldmatrix.sync.aligned.m8n8.x2.shared.b16 {%0,%1},[%2];"
        : "=r"(r[0]),"=r"(r[1]) : "r"(a));
}

// ---------------- gate GEMM (tensor core, ldmatrix) + fused gating ------------
__global__ void __launch_bounds__(256) k_gemm_gate(const float* __restrict__ bg,
                                                   const float* __restrict__ state)
{
    __shared__ __align__(16) __half As[128][KP];
    __shared__ __align__(16) __half Bs[128][KP];

    int row0 = blockIdx.x * 128;
    int b  = row0 / NN;
    int n0 = row0 - b*NN;
    int tid = threadIdx.x;
    int wid = tid >> 5, lane = tid & 31;
    int q = lane & 3, rr_ = lane >> 2;
    int warp_m = wid & 3, warp_n = wid >> 2;

    // ldmatrix per-lane addresses (constant across the m loop)
    unsigned Au[2], At[2], Bu[4], Bt[4];
    #pragma unroll
    for (int mt = 0; mt < 2; mt++) {
        Au[mt] = su32(&As[warp_m*32 + mt*16 + (lane & 15)][(lane >> 4)*8]);
        At[mt] = su32(&As[warp_m*32 + mt*16 + (lane & 15)][64]);
    }
    #pragma unroll
    for (int p = 0; p < 4; p++) {
        Bu[p] = su32(&Bs[warp_n*64 + p*16 + (lane & 7) + ((lane >> 4) & 1)*8][((lane >> 3) & 1)*8]);
        Bt[p] = su32(&Bs[warp_n*64 + p*16 + (lane & 7) + ((lane >> 3) & 1)*8][64]);
    }

    float acc[2][8][4];
    #pragma unroll
    for (int i = 0; i < 2; i++)
        #pragma unroll
        for (int j = 0; j < 8; j++)
            #pragma unroll
            for (int k = 0; k < 4; k++) acc[i][j][k] = 0.f;

    for (int m = 0; m < NMAT; m++) {
        const __half* Xm = g_X + (size_t)m*NN*CROW;
        const __half* Wm = g_Wg_h + m*128*CH;
        __syncthreads();
        for (int idx = tid; idx < 128*9; idx += 256) {
            int rrow = idx / 9, j = idx - rrow*9;
            ((uint4*)&As[rrow][0])[j] = *(const uint4*)(Xm + (size_t)(n0+rrow)*CROW + b*CH + 8*j);
        }
        for (int idx = tid; idx < 128*9; idx += 256) {
            int o = idx / 9, j = idx - o*9;
            ((uint4*)&Bs[o][0])[j] = *(const uint4*)(Wm + o*CH + 8*j);
        }
        __syncthreads();

        #pragma unroll
        for (int ks = 0; ks < 4; ks++) {
            unsigned a0[4], a1[4];
            ldsm4(a0, Au[0] + ks*32);
            ldsm4(a1, Au[1] + ks*32);
            #pragma unroll
            for (int p = 0; p < 4; p++) {
                unsigned bb[4];
                ldsm4(bb, Bu[p] + ks*32);
                mma_16816(acc[0][2*p],   a0, bb);
                mma_16816(acc[0][2*p+1], a0, bb+2);
                mma_16816(acc[1][2*p],   a1, bb);
                mma_16816(acc[1][2*p+1], a1, bb+2);
            }
        }
        {   // k8 tail: k = 64..71 (pads zero)
            unsigned a0[2], a1[2];
            ldsm2(a0, At[0]);
            ldsm2(a1, At[1]);
            #pragma unroll
            for (int p = 0; p < 4; p++) {
                unsigned bt[2];
                ldsm2(bt, Bt[p]);
                mma_1688(acc[0][2*p],   a0, bt[0]);
                mma_1688(acc[0][2*p+1], a0, bt[1]);
                mma_1688(acc[1][2*p],   a1, bt[0]);
                mma_1688(acc[1][2*p+1], a1, bt[1]);
            }
        }
    }

    __half* gX5 = g_X + (size_t)5*NN*CROW;
    #pragma unroll
    for (int mt = 0; mt < 2; mt++) {
        #pragma unroll
        for (int nt = 0; nt < 8; nt++) {
            #pragma unroll
            for (int half_ : {0, 1}) {
                int row_l = warp_m*32 + mt*16 + rr_ + (half_ ? 8 : 0);
                int col   = warp_n*64 + nt*8 + 2*q;
                int n = n0 + row_l;
                float z0 = acc[mt][nt][2*half_+0] + bg[col];
                float z1 = acc[mt][nt][2*half_+1] + bg[col+1];
                float s0 = 1.f/(1.f + expf(-z0));
                float s1 = 1.f/(1.f + expf(-z1));
                if (col < HH) {
                    float2 st = *(const float2*)&state[(size_t)b*NN*HH + (size_t)n*HH + col];
                    __half2 rs = __floats2half2_rn(s0*st.x, s1*st.y);
                    *(__half2*)&gX5[(size_t)n*CROW + b*CH + IND + col] = rs;
                } else {
                    float2 u; u.x = s0; u.y = s1;
                    *(float2*)&g_U[(size_t)(row0+row_l)*HH + (col-HH)] = u;
                }
            }
        }
    }
}

// ---------------- candidate GEMM (tensor core, ldmatrix) + GRU combine --------
__global__ void __launch_bounds__(256) k_gemm_cand(const float* __restrict__ bc,
                                                   const float* __restrict__ state,
                                                   float* __restrict__ out, int dup)
{
    __shared__ __align__(16) __half As[128][KP];
    __shared__ __align__(16) __half Bs[64][KP];

    int row0 = blockIdx.x * 128;
    int b  = row0 / NN;
    int n0 = row0 - b*NN;
    int tid = threadIdx.x;
    int wid = tid >> 5, lane = tid & 31;
    int q = lane & 3, rr_ = lane >> 2;
    int warp_m = wid & 3, warp_n = wid >> 2;

    unsigned Au[2], At[2], Bu[2], Bt[2];
    #pragma unroll
    for (int mt = 0; mt < 2; mt++) {
        Au[mt] = su32(&As[warp_m*32 + mt*16 + (lane & 15)][(lane >> 4)*8]);
        At[mt] = su32(&As[warp_m*32 + mt*16 + (lane & 15)][64]);
    }
    #pragma unroll
    for (int p = 0; p < 2; p++) {
        Bu[p] = su32(&Bs[warp_n*32 + p*16 + (lane & 7) + ((lane >> 4) & 1)*8][((lane >> 3) & 1)*8]);
        Bt[p] = su32(&Bs[warp_n*32 + p*16 + (lane & 7) + ((lane >> 3) & 1)*8][64]);
    }

    float acc[2][4][4];
    #pragma unroll
    for (int i = 0; i < 2; i++)
        #pragma unroll
        for (int j = 0; j < 4; j++)
            #pragma unroll
            for (int k = 0; k < 4; k++) acc[i][j][k] = 0.f;

    for (int m = 0; m < NMAT; m++) {
        const __half* Xm = g_X + (size_t)(5+m)*NN*CROW;
        const __half* Wm = g_Wc_h + m*64*CH;
        __syncthreads();
        for (int idx = tid; idx < 128*9; idx += 256) {
            int rrow = idx / 9, j = idx - rrow*9;
            ((uint4*)&As[rrow][0])[j] = *(const uint4*)(Xm + (size_t)(n0+rrow)*CROW + b*CH + 8*j);
        }
        for (int idx = tid; idx < 64*9; idx += 256) {
            int o = idx / 9, j = idx - o*9;
            ((uint4*)&Bs[o][0])[j] = *(const uint4*)(Wm + o*CH + 8*j);
        }
        __syncthreads();

        #pragma unroll
        for (int ks = 0; ks < 4; ks++) {
            unsigned a0[4], a1[4];
            ldsm4(a0, Au[0] + ks*32);
            ldsm4(a1, Au[1] + ks*32);
            #pragma unroll
            for (int p = 0; p < 2; p++) {
                unsigned bb[4];
                ldsm4(bb, Bu[p] + ks*32);
                mma_16816(acc[0][2*p],   a0, bb);
                mma_16816(acc[0][2*p+1], a0, bb+2);
                mma_16816(acc[1][2*p],   a1, bb);
                mma_16816(acc[1][2*p+1], a1, bb+2);
            }
        }
        {
            unsigned a0[2], a1[2];
            ldsm2(a0, At[0]);
            ldsm2(a1, At[1]);
            #pragma unroll
            for (int p = 0; p < 2; p++) {
                unsigned bt[2];
                ldsm2(bt, Bt[p]);
                mma_1688(acc[0][2*p],   a0, bt[0]);
                mma_1688(acc[0][2*p+1], a0, bt[1]);
                mma_1688(acc[1][2*p],   a1, bt[0]);
                mma_1688(acc[1][2*p+1], a1, bt[1]);
            }
        }
    }

    #pragma unroll
    for (int mt = 0; mt < 2; mt++) {
        #pragma unroll
        for (int nt = 0; nt < 4; nt++) {
            #pragma unroll
            for (int half_ : {0, 1}) {
                int row_l = warp_m*32 + mt*16 + rr_ + (half_ ? 8 : 0);
                int col   = warp_n*32 + nt*8 + 2*q;
                int n = n0 + row_l;
                int row = row0 + row_l;
                float c0 = tanhf(acc[mt][nt][2*half_+0] + bc[col]);
                float c1 = tanhf(acc[mt][nt][2*half_+1] + bc[col+1]);
                size_t sidx = (size_t)b*NN*HH + (size_t)n*HH + col;
                float2 u  = *(const float2*)&g_U[(size_t)row*HH + col];
                float2 st = *(const float2*)&state[sidx];
                float2 ns;
                ns.x = u.x*st.x + (1.f - u.x)*c0;
                ns.y = u.y*st.y + (1.f - u.y)*c1;
                *(float2*)&out[sidx] = ns;
                if (dup) *(float2*)&out[sidx + (size_t)BB*NN*HH] = ns;
            }
        }
    }
}

// ---------------- launch ------------------------------------------------------
extern "C" void kernel_launch(void* const* d_in, const int* in_sizes, int n_in,
                              void* d_out, int out_size)
{
    const float* inputs = (const float*)d_in[0];
    const float* state  = (const float*)d_in[1];
    const int*   esrc   = (const int*)  d_in[2];
    const int*   edst   = (const int*)  d_in[3];
    const float* v1     = (const float*)d_in[4];
    const float* v2     = (const float*)d_in[5];
    const float* Wg     = (const float*)d_in[6];
    const float* bg     = (const float*)d_in[7];
    const float* Wc     = (const float*)d_in[8];
    const float* bc     = (const float*)d_in[9];
    float* out = (float*)d_out;
    int dup = (out_size >= 2*BB*NN*HH) ? 1 : 0;

    k_zero<<<NN/256, 256>>>();
    k_count<<<EE/256, 256>>>(esrc, edst);
    k_scan<<<1, 1024>>>();
    k_scatter<<<EE/256, 256>>>(esrc, edst);
    k_sortfill<<<NN/256, 256>>>(esrc, edst, v1, v2);

    size_t init_total = (size_t)NN*CROW + (size_t)NMAT*128*CH + (size_t)NMAT*64*CH;
    k_init<<<(unsigned)((init_total + 255)/256), 256>>>(inputs, state, Wg, Wc);

    // gate diffusion: X1 = A1 X0 ; X3 = A2 X0 ; then Y2 = A1 X1 ; Y4 = A2 X3
    k_spmm2<<<dim3(NN/2,2), 256>>>(0,0,1,  1,0,3);
    k_spmm2<<<dim3(NN/2,2), 256>>>(0,1,2,  1,3,4);

    k_gemm_gate<<<(BB*NN)/128, 256>>>(bg, state);

    // candidate diffusion on Xc0 = concat(inputs, r*state) (buffer 5)
    k_spmm2<<<dim3(NN/2,2), 256>>>(0,5,6,  1,5,8);
    k_spmm2<<<dim3(NN/2,2), 256>>>(0,6,7,  1,8,9);

    k_gemm_cand<<<(BB*NN)/128, 256>>>(bc, state, out, dup);
}

// round 5
// speedup vs baseline: 2.3609x; 1.1600x over previous
#include <cuda_runtime.h>
#include <cuda_fp16.h>
#include <math.h>

#define NN   8192
#define BB   16
#define IND  2
#define HH   64
#define FF   66
#define EE   131072
#define NMAT 5
#define KP   72
// state-part row: 16 batches * 64 halves = 1024 halves = 2048 B = 128 uint4
#define SROW 1024
#define SV4  128
// input-part row: 16 batches * 2 halves = 32 halves = 64 B = 4 uint4
#define IROW 32

// ---------------- device scratch (static) ------------------------------------
__device__ __half g_Xs[(size_t)10*NN*SROW];   // state-part bufs: 0..4 gate, 5..9 cand
__device__ __half g_Xin[(size_t)5*NN*IROW];   // input-part bufs (shared by both passes)
__device__ float  g_U[(size_t)BB*NN*HH];
__device__ __half g_Wg_h[NMAT*128*KP];        // folded, K-permuted (state first)
__device__ __half g_Wc_h[NMAT*64*KP];
__device__ int   g_cnt[2][NN];
__device__ int   g_cur[2][NN];
__device__ int   g_ptr[2][NN+1];
__device__ int   g_eidx[2][EE];
__device__ int2  g_cw[2][EE];

// ---------------- CSR build (deterministic) ---------------------------------
__global__ void k_zero()
{
    int i = blockIdx.x*blockDim.x + threadIdx.x;
    if (i < NN) { g_cnt[0][i]=0; g_cnt[1][i]=0; g_cur[0][i]=0; g_cur[1][i]=0; }
}

__global__ void k_count(const int* __restrict__ src, const int* __restrict__ dst)
{
    int e = blockIdx.x*blockDim.x + threadIdx.x;
    if (e < EE) {
        atomicAdd(&g_cnt[0][src[e]], 1);
        atomicAdd(&g_cnt[1][dst[e]], 1);
    }
}

__global__ void k_scan()   // 1 block, 1024 threads, warp-shuffle scan
{
    __shared__ int wsum[32];
    int tid = threadIdx.x, lane = tid & 31, wrp = tid >> 5;
    for (int m = 0; m < 2; m++) {
        int base = tid*8;
        int c[8];
        int s_local = 0;
        #pragma unroll
        for (int j = 0; j < 8; j++) { c[j] = g_cnt[m][base+j]; s_local += c[j]; }
        int v = s_local;
        #pragma unroll
        for (int off = 1; off < 32; off <<= 1) {
            int o = __shfl_up_sync(0xffffffffu, v, off);
            if (lane >= off) v += o;
        }
        if (lane == 31) wsum[wrp] = v;
        __syncthreads();
        if (wrp == 0) {
            int w = (lane < 32) ? wsum[lane] : 0;
            #pragma unroll
            for (int off = 1; off < 32; off <<= 1) {
                int o = __shfl_up_sync(0xffffffffu, w, off);
                if (lane >= off) w += o;
            }
            wsum[lane] = w;
        }
        __syncthreads();
        int run = v - s_local + (wrp ? wsum[wrp-1] : 0);   // exclusive prefix
        #pragma unroll
        for (int j = 0; j < 8; j++) { g_ptr[m][base+j] = run; run += c[j]; }
        if (tid == 1023) g_ptr[m][NN] = run;
        __syncthreads();
    }
}

__global__ void k_scatter(const int* __restrict__ src, const int* __restrict__ dst)
{
    int e = blockIdx.x*blockDim.x + threadIdx.x;
    if (e < EE) {
        int r = src[e];
        int p = g_ptr[0][r] + atomicAdd(&g_cur[0][r], 1);
        g_eidx[0][p] = e;
        r = dst[e];
        p = g_ptr[1][r] + atomicAdd(&g_cur[1][r], 1);
        g_eidx[1][p] = e;
    }
}

__global__ void k_sortfill(const int* __restrict__ src, const int* __restrict__ dst,
                           const float* __restrict__ v1, const float* __restrict__ v2)
{
    int r = blockIdx.x*blockDim.x + threadIdx.x;
    int m = blockIdx.y;
    if (r >= NN) return;
    int beg = g_ptr[m][r], end = g_ptr[m][r+1];
    for (int i = beg+1; i < end; i++) {
        int key = g_eidx[m][i];
        int j = i-1;
        while (j >= beg && g_eidx[m][j] > key) { g_eidx[m][j+1] = g_eidx[m][j]; j--; }
        g_eidx[m][j+1] = key;
    }
    for (int i = beg; i < end; i++) {
        int e = g_eidx[m][i];
        int2 cw;
        if (m == 0) { cw.x = dst[e]; cw.y = __float_as_int(v1[e]); }
        else        { cw.x = src[e]; cw.y = __float_as_int(v2[e]); }
        g_cw[m][i] = cw;
    }
}

// ---------------- init: Xs0, Xin0, folded+permuted weights -------------------
// K order: k in [0,64) -> state feature k (orig f = k+2); k in [64,66) -> input
// feature k-64 (orig f = k-64); k in [66,72) -> zero pad.
// Chebyshev fold: W0' = W0 - W2 - W4 ; W2' = 2*W2 ; W4' = 2*W4.
__global__ void k_init(const float* __restrict__ inputs, const float* __restrict__ state,
                       const float* __restrict__ Wg, const float* __restrict__ Wc)
{
    const size_t T1 = (size_t)NN*SROW;
    const size_t T2 = T1 + (size_t)NN*IROW;
    const size_t T3 = T2 + (size_t)NMAT*128*KP;
    size_t idx = (size_t)blockIdx.x*blockDim.x + threadIdx.x;
    if (idx < T1) {
        int n = (int)(idx / SROW);
        int c = (int)(idx - (size_t)n*SROW);
        int b = c >> 6, h = c & 63;
        g_Xs[idx] = __float2half_rn(state[(size_t)b*NN*HH + (size_t)n*HH + h]);
    } else if (idx < T2) {
        size_t i1 = idx - T1;
        int n = (int)(i1 / IROW);
        int c = (int)(i1 - (size_t)n*IROW);
        int b = c >> 1, j = c & 1;
        g_Xin[i1] = __float2half_rn(inputs[(size_t)b*NN*IND + (size_t)n*IND + j]);
    } else if (idx < T3) {
        size_t i2 = idx - T2;
        int m = (int)(i2 / (128*KP));
        int rem = (int)(i2 - (size_t)m*(128*KP));
        int o = rem / KP, k = rem - o*KP;
        float w = 0.f;
        if (k < 66) {
            int f = (k < 64) ? (k + IND) : (k - 64);
            const float* base = Wg + (size_t)(f*NMAT)*128 + o;
            if      (m == 0) w = base[0] - base[2*128] - base[4*128];
            else if (m == 2) w = 2.f*base[2*128];
            else if (m == 4) w = 2.f*base[4*128];
            else             w = base[m*128];
        }
        g_Wg_h[i2] = __float2half_rn(w);
    } else if (idx < T3 + (size_t)NMAT*64*KP) {
        size_t i3 = idx - T3;
        int m = (int)(i3 / (64*KP));
        int rem = (int)(i3 - (size_t)m*(64*KP));
        int o = rem / KP, k = rem - o*KP;
        float w = 0.f;
        if (k < 66) {
            int f = (k < 64) ? (k + IND) : (k - 64);
            const float* base = Wc + (size_t)(f*NMAT)*64 + o;
            if      (m == 0) w = base[0] - base[2*64] - base[4*64];
            else if (m == 2) w = 2.f*base[2*64];
            else if (m == 4) w = 2.f*base[4*64];
            else             w = base[m*64];
        }
        g_Wc_h[i3] = __float2half_rn(w);
    }
}

// ---------------- state-part SPMM: Y = A_m X ---------------------------------
__device__ __forceinline__ void acc8(float* a, float w, uint4 h)
{
    float2 p0 = __half22float2(*(const __half2*)&h.x);
    float2 p1 = __half22float2(*(const __half2*)&h.y);
    float2 p2 = __half22float2(*(const __half2*)&h.z);
    float2 p3 = __half22float2(*(const __half2*)&h.w);
    a[0] += w*p0.x; a[1] += w*p0.y; a[2] += w*p1.x; a[3] += w*p1.y;
    a[4] += w*p2.x; a[5] += w*p2.y; a[6] += w*p3.x; a[7] += w*p3.y;
}

__global__ void __launch_bounds__(256) k_spmm_s(int m0,int xi0,int yi0,
                                                int m1,int xi1,int yi1)
{
    int which = blockIdx.y;
    int m  = which ? m1  : m0;
    int xi = which ? xi1 : xi0;
    int yi = which ? yi1 : yi0;

    const uint4* __restrict__ X = (const uint4*)(g_Xs + (size_t)xi*NN*SROW);
    uint4*       __restrict__ Y = (uint4*)      (g_Xs + (size_t)yi*NN*SROW);

    int sub = threadIdx.x >> 7;
    int t   = threadIdx.x & 127;
    int r   = blockIdx.x*2 + sub;
    int beg = g_ptr[m][r], end = g_ptr[m][r+1];
    const int2* __restrict__ cw = g_cw[m];

    float acc[8] = {0.f,0.f,0.f,0.f,0.f,0.f,0.f,0.f};

    int j = beg;
    for (; j + 8 <= end; j += 8) {
        int2 e[8];
        #pragma unroll
        for (int u = 0; u < 8; u++) e[u] = __ldg(cw + j + u);
        uint4 h[8];
        #pragma unroll
        for (int u = 0; u < 8; u++) h[u] = __ldg(X + (size_t)e[u].x*SV4 + t);
        #pragma unroll
        for (int u = 0; u < 8; u++) acc8(acc, __int_as_float(e[u].y), h[u]);
    }
    for (; j < end; j++) {
        int2 e = __ldg(cw + j);
        uint4 h = __ldg(X + (size_t)e.x*SV4 + t);
        acc8(acc, __int_as_float(e.y), h);
    }

    __half2 a0 = __floats2half2_rn(acc[0],acc[1]);
    __half2 a1 = __floats2half2_rn(acc[2],acc[3]);
    __half2 a2 = __floats2half2_rn(acc[4],acc[5]);
    __half2 a3 = __floats2half2_rn(acc[6],acc[7]);
    uint4 st; st.x=*(unsigned*)&a0; st.y=*(unsigned*)&a1; st.z=*(unsigned*)&a2; st.w=*(unsigned*)&a3;
    Y[(size_t)r*SV4 + t] = st;
}

// ---------------- input-part SPMM (tiny rows: 4 uint4) -----------------------
__global__ void __launch_bounds__(256) k_spmm_in(int xi0,int yi0, int xi1,int yi1)
{
    int m  = blockIdx.y;
    int xi = m ? xi1 : xi0;
    int yi = m ? yi1 : yi0;
    const uint4* __restrict__ X = (const uint4*)(g_Xin + (size_t)xi*NN*IROW);
    uint4*       __restrict__ Y = (uint4*)      (g_Xin + (size_t)yi*NN*IROW);

    int r = blockIdx.x*64 + (threadIdx.x >> 2);
    int q = threadIdx.x & 3;
    int beg = g_ptr[m][r], end = g_ptr[m][r+1];
    const int2* __restrict__ cw = g_cw[m];

    float acc[8] = {0.f,0.f,0.f,0.f,0.f,0.f,0.f,0.f};
    for (int j = beg; j < end; j++) {
        int2 e = __ldg(cw + j);
        uint4 h = __ldg(X + (size_t)e.x*4 + q);
        acc8(acc, __int_as_float(e.y), h);
    }
    __half2 a0 = __floats2half2_rn(acc[0],acc[1]);
    __half2 a1 = __floats2half2_rn(acc[2],acc[3]);
    __half2 a2 = __floats2half2_rn(acc[4],acc[5]);
    __half2 a3 = __floats2half2_rn(acc[6],acc[7]);
    uint4 st; st.x=*(unsigned*)&a0; st.y=*(unsigned*)&a1; st.z=*(unsigned*)&a2; st.w=*(unsigned*)&a3;
    Y[(size_t)r*4 + q] = st;
}

// ---------------- MMA / ldmatrix helpers --------------------------------------
__device__ __forceinline__ void mma_16816(float c[4], const unsigned a[4], const unsigned b[2]) {
    asm volatile(
        "mma.sync.aligned.m16n8k16.row.col.f32.f16.f16.f32 "
        "{%0,%1,%2,%3},{%4,%5,%6,%7},{%8,%9},{%0,%1,%2,%3};\n"
        : "+f"(c[0]), "+f"(c[1]), "+f"(c[2]), "+f"(c[3])
        : "r"(a[0]), "r"(a[1]), "r"(a[2]), "r"(a[3]), "r"(b[0]), "r"(b[1]));
}
__device__ __forceinline__ void mma_1688(float c[4], const unsigned a[2], const unsigned b0) {
    asm volatile(
        "mma.sync.aligned.m16n8k8.row.col.f32.f16.f16.f32 "
        "{%0,%1,%2,%3},{%4,%5},{%6},{%0,%1,%2,%3};\n"
        : "+f"(c[0]), "+f"(c[1]), "+f"(c[2]), "+f"(c[3])
        : "r"(a[0]), "r"(a[1]), "r"(b0));
}
__device__ __forceinline__ unsigned su32(const void* p) {
    return (unsigned)__cvta_generic_to_shared(p);
}
__device__ __forceinline__ void ldsm4(unsigned* r, unsigned a) {
    asm volatile("ldmatrix.sync.aligned.m8n8.x4.shared.b16 {%0,%1,%2,%3},[%4];"
        : "=r"(r[0]),"=r"(r[1]),"=r"(r[2]),"=r"(r[3]) : "r"(a));
}
__device__ __forceinline__ void ldsm2(unsigned* r, unsigned a) {
    asm volatile("ldmatrix.sync.aligned.m8n8.x2.shared.b16 {%0,%1},[%2];"
        : "=r"(r[0]),"=r"(r[1]) : "r"(a));
}

// ---------------- gate GEMM + fused gating ------------------------------------
__global__ void __launch_bounds__(256) k_gemm_gate(const float* __restrict__ bg,
                                                   const float* __restrict__ state)
{
    __shared__ __align__(16) __half As[128][KP];
    __shared__ __align__(16) __half Bs[128][KP];

    int row0 = blockIdx.x * 128;
    int b  = row0 / NN;
    int n0 = row0 - b*NN;
    int tid = threadIdx.x;
    int wid = tid >> 5, lane = tid & 31;
    int q = lane & 3, rr_ = lane >> 2;
    int warp_m = wid & 3, warp_n = wid >> 2;

    unsigned Au[2], At[2], Bu[4], Bt[4];
    #pragma unroll
    for (int mt = 0; mt < 2; mt++) {
        Au[mt] = su32(&As[warp_m*32 + mt*16 + (lane & 15)][(lane >> 4)*8]);
        At[mt] = su32(&As[warp_m*32 + mt*16 + (lane & 15)][64]);
    }
    #pragma unroll
    for (int p = 0; p < 4; p++) {
        Bu[p] = su32(&Bs[warp_n*64 + p*16 + (lane & 7) + ((lane >> 4) & 1)*8][((lane >> 3) & 1)*8]);
        Bt[p] = su32(&Bs[warp_n*64 + p*16 + (lane & 7) + ((lane >> 3) & 1)*8][64]);
    }

    float acc[2][8][4];
    #pragma unroll
    for (int i = 0; i < 2; i++)
        #pragma unroll
        for (int j = 0; j < 8; j++)
            #pragma unroll
            for (int k = 0; k < 4; k++) acc[i][j][k] = 0.f;

    for (int m = 0; m < NMAT; m++) {
        const uint4* Xs  = (const uint4*)(g_Xs + (size_t)m*NN*SROW);
        const __half* Xin = g_Xin + (size_t)m*NN*IROW;
        const __half* Wm  = g_Wg_h + m*128*KP;
        __syncthreads();
        for (int idx = tid; idx < 128*9; idx += 256) {
            int rrow = idx / 9, j = idx - rrow*9;
            uint4 v;
            if (j < 8) v = Xs[(size_t)(n0+rrow)*SV4 + b*8 + j];
            else {
                v.x = *(const unsigned*)(Xin + (size_t)(n0+rrow)*IROW + b*2);
                v.y = 0u; v.z = 0u; v.w = 0u;
            }
            ((uint4*)&As[rrow][0])[j] = v;
        }
        for (int idx = tid; idx < 128*9; idx += 256) {
            int o = idx / 9, j = idx - o*9;
            ((uint4*)&Bs[o][0])[j] = *(const uint4*)(Wm + o*KP + 8*j);
        }
        __syncthreads();

        #pragma unroll
        for (int ks = 0; ks < 4; ks++) {
            unsigned a0[4], a1[4];
            ldsm4(a0, Au[0] + ks*32);
            ldsm4(a1, Au[1] + ks*32);
            #pragma unroll
            for (int p = 0; p < 4; p++) {
                unsigned bb[4];
                ldsm4(bb, Bu[p] + ks*32);
                mma_16816(acc[0][2*p],   a0, bb);
                mma_16816(acc[0][2*p+1], a0, bb+2);
                mma_16816(acc[1][2*p],   a1, bb);
                mma_16816(acc[1][2*p+1], a1, bb+2);
            }
        }
        {
            unsigned a0[2], a1[2];
            ldsm2(a0, At[0]);
            ldsm2(a1, At[1]);
            #pragma unroll
            for (int p = 0; p < 4; p++) {
                unsigned bt[2];
                ldsm2(bt, Bt[p]);
                mma_1688(acc[0][2*p],   a0, bt[0]);
                mma_1688(acc[0][2*p+1], a0, bt[1]);
                mma_1688(acc[1][2*p],   a1, bt[0]);
                mma_1688(acc[1][2*p+1], a1, bt[1]);
            }
        }
    }

    __half* Xc0 = g_Xs + (size_t)5*NN*SROW;   // candidate state-part x0 = r*state
    #pragma unroll
    for (int mt = 0; mt < 2; mt++) {
        #pragma unroll
        for (int nt = 0; nt < 8; nt++) {
            #pragma unroll
            for (int half_ : {0, 1}) {
                int row_l = warp_m*32 + mt*16 + rr_ + (half_ ? 8 : 0);
                int col   = warp_n*64 + nt*8 + 2*q;
                int n = n0 + row_l;
                float z0 = acc[mt][nt][2*half_+0] + bg[col];
                float z1 = acc[mt][nt][2*half_+1] + bg[col+1];
                float s0 = 1.f/(1.f + expf(-z0));
                float s1 = 1.f/(1.f + expf(-z1));
                if (col < HH) {
                    float2 st = *(const float2*)&state[(size_t)b*NN*HH + (size_t)n*HH + col];
                    __half2 rs = __floats2half2_rn(s0*st.x, s1*st.y);
                    *(__half2*)&Xc0[(size_t)n*SROW + b*HH + col] = rs;
                } else {
                    float2 u; u.x = s0; u.y = s1;
                    *(float2*)&g_U[(size_t)(row0+row_l)*HH + (col-HH)] = u;
                }
            }
        }
    }
}

// ---------------- candidate GEMM + GRU combine --------------------------------
__global__ void __launch_bounds__(256) k_gemm_cand(const float* __restrict__ bc,
                                                   const float* __restrict__ state,
                                                   float* __restrict__ out, int dup)
{
    __shared__ __align__(16) __half As[128][KP];
    __shared__ __align__(16) __half Bs[64][KP];

    int row0 = blockIdx.x * 128;
    int b  = row0 / NN;
    int n0 = row0 - b*NN;
    int tid = threadIdx.x;
    int wid = tid >> 5, lane = tid & 31;
    int q = lane & 3, rr_ = lane >> 2;
    int warp_m = wid & 3, warp_n = wid >> 2;

    unsigned Au[2], At[2], Bu[2], Bt[2];
    #pragma unroll
    for (int mt = 0; mt < 2; mt++) {
        Au[mt] = su32(&As[warp_m*32 + mt*16 + (lane & 15)][(lane >> 4)*8]);
        At[mt] = su32(&As[warp_m*32 + mt*16 + (lane & 15)][64]);
    }
    #pragma unroll
    for (int p = 0; p < 2; p++) {
        Bu[p] = su32(&Bs[warp_n*32 + p*16 + (lane & 7) + ((lane >> 4) & 1)*8][((lane >> 3) & 1)*8]);
        Bt[p] = su32(&Bs[warp_n*32 + p*16 + (lane & 7) + ((lane >> 3) & 1)*8][64]);
    }

    float acc[2][4][4];
    #pragma unroll
    for (int i = 0; i < 2; i++)
        #pragma unroll
        for (int j = 0; j < 4; j++)
            #pragma unroll
            for (int k = 0; k < 4; k++) acc[i][j][k] = 0.f;

    for (int m = 0; m < NMAT; m++) {
        const uint4* Xs  = (const uint4*)(g_Xs + (size_t)(5+m)*NN*SROW);
        const __half* Xin = g_Xin + (size_t)m*NN*IROW;   // shared with gate pass
        const __half* Wm  = g_Wc_h + m*64*KP;
        __syncthreads();
        for (int idx = tid; idx < 128*9; idx += 256) {
            int rrow = idx / 9, j = idx - rrow*9;
            uint4 v;
            if (j < 8) v = Xs[(size_t)(n0+rrow)*SV4 + b*8 + j];
            else {
                v.x = *(const unsigned*)(Xin + (size_t)(n0+rrow)*IROW + b*2);
                v.y = 0u; v.z = 0u; v.w = 0u;
            }
            ((uint4*)&As[rrow][0])[j] = v;
        }
        for (int idx = tid; idx < 64*9; idx += 256) {
            int o = idx / 9, j = idx - o*9;
            ((uint4*)&Bs[o][0])[j] = *(const uint4*)(Wm + o*KP + 8*j);
        }
        __syncthreads();

        #pragma unroll
        for (int ks = 0; ks < 4; ks++) {
            unsigned a0[4], a1[4];
            ldsm4(a0, Au[0] + ks*32);
            ldsm4(a1, Au[1] + ks*32);
            #pragma unroll
            for (int p = 0; p < 2; p++) {
                unsigned bb[4];
                ldsm4(bb, Bu[p] + ks*32);
                mma_16816(acc[0][2*p],   a0, bb);
                mma_16816(acc[0][2*p+1], a0, bb+2);
                mma_16816(acc[1][2*p],   a1, bb);
                mma_16816(acc[1][2*p+1], a1, bb+2);
            }
        }
        {
            unsigned a0[2], a1[2];
            ldsm2(a0, At[0]);
            ldsm2(a1, At[1]);
            #pragma unroll
            for (int p = 0; p < 2; p++) {
                unsigned bt[2];
                ldsm2(bt, Bt[p]);
                mma_1688(acc[0][2*p],   a0, bt[0]);
                mma_1688(acc[0][2*p+1], a0, bt[1]);
                mma_1688(acc[1][2*p],   a1, bt[0]);
                mma_1688(acc[1][2*p+1], a1, bt[1]);
            }
        }
    }

    #pragma unroll
    for (int mt = 0; mt < 2; mt++) {
        #pragma unroll
        for (int nt = 0; nt < 4; nt++) {
            #pragma unroll
            for (int half_ : {0, 1}) {
                int row_l = warp_m*32 + mt*16 + rr_ + (half_ ? 8 : 0);
                int col   = warp_n*32 + nt*8 + 2*q;
                int n = n0 + row_l;
                int row = row0 + row_l;
                float c0 = tanhf(acc[mt][nt][2*half_+0] + bc[col]);
                float c1 = tanhf(acc[mt][nt][2*half_+1] + bc[col+1]);
                size_t sidx = (size_t)b*NN*HH + (size_t)n*HH + col;
                float2 u  = *(const float2*)&g_U[(size_t)row*HH + col];
                float2 st = *(const float2*)&state[sidx];
                float2 ns;
                ns.x = u.x*st.x + (1.f - u.x)*c0;
                ns.y = u.y*st.y + (1.f - u.y)*c1;
                *(float2*)&out[sidx] = ns;
                if (dup) *(float2*)&out[sidx + (size_t)BB*NN*HH] = ns;
            }
        }
    }
}

// ---------------- launch ------------------------------------------------------
extern "C" void kernel_launch(void* const* d_in, const int* in_sizes, int n_in,
                              void* d_out, int out_size)
{
    const float* inputs = (const float*)d_in[0];
    const float* state  = (const float*)d_in[1];
    const int*   esrc   = (const int*)  d_in[2];
    const int*   edst   = (const int*)  d_in[3];
    const float* v1     = (const float*)d_in[4];
    const float* v2     = (const float*)d_in[5];
    const float* Wg     = (const float*)d_in[6];
    const float* bg     = (const float*)d_in[7];
    const float* Wc     = (const float*)d_in[8];
    const float* bc     = (const float*)d_in[9];
    float* out = (float*)d_out;
    int dup = (out_size >= 2*BB*NN*HH) ? 1 : 0;

    k_zero<<<NN/256, 256>>>();
    k_count<<<EE/256, 256>>>(esrc, edst);
    k_scan<<<1, 1024>>>();
    k_scatter<<<EE/256, 256>>>(esrc, edst);
    k_sortfill<<<dim3(NN/256,2), 256>>>(esrc, edst, v1, v2);

    size_t init_total = (size_t)NN*SROW + (size_t)NN*IROW
                      + (size_t)NMAT*128*KP + (size_t)NMAT*64*KP;
    k_init<<<(unsigned)((init_total + 255)/256), 256>>>(inputs, state, Wg, Wc);

    // input-part diffusion (shared by both passes): Xin1=A1 Xin0, Xin3=A2 Xin0;
    // Xin2=A1 Xin1, Xin4=A2 Xin3
    k_spmm_in<<<dim3(NN/64,2), 256>>>(0,1, 0,3);
    k_spmm_in<<<dim3(NN/64,2), 256>>>(1,2, 3,4);

    // gate state-part diffusion
    k_spmm_s<<<dim3(NN/2,2), 256>>>(0,0,1,  1,0,3);
    k_spmm_s<<<dim3(NN/2,2), 256>>>(0,1,2,  1,3,4);

    k_gemm_gate<<<(BB*NN)/128, 256>>>(bg, state);

    // candidate state-part diffusion on Xc0 = r*state (buffer 5)
    k_spmm_s<<<dim3(NN/2,2), 256>>>(0,5,6,  1,5,8);
    k_spmm_s<<<dim3(NN/2,2), 256>>>(0,6,7,  1,8,9);

    k_gemm_cand<<<(BB*NN)/128, 256>>>(bc, state, out, dup);
}

// round 6
// speedup vs baseline: 2.7578x; 1.1681x over previous
#include <cuda_runtime.h>
#include <cuda_fp16.h>
#include <math.h>

#define NN   8192
#define BB   16
#define IND  2
#define HH   64
#define FF   66
#define EE   131072
#define NMAT 5
#define KP   72
#define SROW 1024     // 16 batches * 64 halves = 2048 B
#define SV4  128      // uint4 per state row
#define IROW 32       // 16 batches * 2 halves = 64 B
#define INBLK (NN/32) // input-part blocks (32 rows per 128-thread block)

// ---------------- device scratch (static) ------------------------------------
__device__ __half g_Xs[(size_t)10*NN*SROW];
__device__ __half g_Xin[(size_t)5*NN*IROW];
__device__ float  g_U[(size_t)BB*NN*HH];
__device__ __half g_Wg_h[NMAT*128*KP];
__device__ __half g_Wc_h[NMAT*64*KP];
__device__ int   g_cnt[2][NN];
__device__ int   g_cur[2][NN];
__device__ int   g_ptr[2][NN+1];
__device__ int   g_eidx[2][EE];
__device__ int2  g_cw[2][EE];

// ---------------- CSR build (deterministic) ----------------------------------
__global__ void k_count(const int* __restrict__ src, const int* __restrict__ dst)
{
    int e = blockIdx.x*blockDim.x + threadIdx.x;
    if (e < EE) {
        atomicAdd(&g_cnt[0][src[e]], 1);
        atomicAdd(&g_cnt[1][dst[e]], 1);
    }
}

__global__ void k_scan()
{
    __shared__ int wsum[32];
    int tid = threadIdx.x, lane = tid & 31, wrp = tid >> 5;
    for (int m = 0; m < 2; m++) {
        int base = tid*8;
        int c[8];
        int s_local = 0;
        #pragma unroll
        for (int j = 0; j < 8; j++) { c[j] = g_cnt[m][base+j]; s_local += c[j]; }
        int v = s_local;
        #pragma unroll
        for (int off = 1; off < 32; off <<= 1) {
            int o = __shfl_up_sync(0xffffffffu, v, off);
            if (lane >= off) v += o;
        }
        if (lane == 31) wsum[wrp] = v;
        __syncthreads();
        if (wrp == 0) {
            int w = wsum[lane];
            #pragma unroll
            for (int off = 1; off < 32; off <<= 1) {
                int o = __shfl_up_sync(0xffffffffu, w, off);
                if (lane >= off) w += o;
            }
            wsum[lane] = w;
        }
        __syncthreads();
        int run = v - s_local + (wrp ? wsum[wrp-1] : 0);
        #pragma unroll
        for (int j = 0; j < 8; j++) { g_ptr[m][base+j] = run; run += c[j]; }
        if (tid == 1023) g_ptr[m][NN] = run;
        __syncthreads();
    }
}

__global__ void k_scatter(const int* __restrict__ src, const int* __restrict__ dst)
{
    int e = blockIdx.x*blockDim.x + threadIdx.x;
    if (e < EE) {
        int r = src[e];
        int p = g_ptr[0][r] + atomicAdd(&g_cur[0][r], 1);
        g_eidx[0][p] = e;
        r = dst[e];
        p = g_ptr[1][r] + atomicAdd(&g_cur[1][r], 1);
        g_eidx[1][p] = e;
    }
}

__global__ void k_sortfill(const int* __restrict__ src, const int* __restrict__ dst,
                           const float* __restrict__ v1, const float* __restrict__ v2)
{
    int r = blockIdx.x*blockDim.x + threadIdx.x;
    int m = blockIdx.y;
    if (r >= NN) return;
    int beg = g_ptr[m][r], end = g_ptr[m][r+1];
    for (int i = beg+1; i < end; i++) {
        int key = g_eidx[m][i];
        int j = i-1;
        while (j >= beg && g_eidx[m][j] > key) { g_eidx[m][j+1] = g_eidx[m][j]; j--; }
        g_eidx[m][j+1] = key;
    }
    for (int i = beg; i < end; i++) {
        int e = g_eidx[m][i];
        int2 cw;
        if (m == 0) { cw.x = dst[e]; cw.y = __float_as_int(v1[e]); }
        else        { cw.x = src[e]; cw.y = __float_as_int(v2[e]); }
        g_cw[m][i] = cw;
    }
}

// ---------------- init: Xs0, Xin0, folded+permuted weights -------------------
__global__ void k_init(const float* __restrict__ inputs, const float* __restrict__ state,
                       const float* __restrict__ Wg, const float* __restrict__ Wc)
{
    const size_t T1 = (size_t)NN*SROW;
    const size_t T2 = T1 + (size_t)NN*IROW;
    const size_t T3 = T2 + (size_t)NMAT*128*KP;
    size_t idx = (size_t)blockIdx.x*blockDim.x + threadIdx.x;
    if (idx < T1) {
        int n = (int)(idx / SROW);
        int c = (int)(idx - (size_t)n*SROW);
        int b = c >> 6, h = c & 63;
        g_Xs[idx] = __float2half_rn(state[(size_t)b*NN*HH + (size_t)n*HH + h]);
    } else if (idx < T2) {
        size_t i1 = idx - T1;
        int n = (int)(i1 / IROW);
        int c = (int)(i1 - (size_t)n*IROW);
        int b = c >> 1, j = c & 1;
        g_Xin[i1] = __float2half_rn(inputs[(size_t)b*NN*IND + (size_t)n*IND + j]);
    } else if (idx < T3) {
        size_t i2 = idx - T2;
        int m = (int)(i2 / (128*KP));
        int rem = (int)(i2 - (size_t)m*(128*KP));
        int o = rem / KP, k = rem - o*KP;
        float w = 0.f;
        if (k < 66) {
            int f = (k < 64) ? (k + IND) : (k - 64);
            const float* base = Wg + (size_t)(f*NMAT)*128 + o;
            if      (m == 0) w = base[0] - base[2*128] - base[4*128];
            else if (m == 2) w = 2.f*base[2*128];
            else if (m == 4) w = 2.f*base[4*128];
            else             w = base[m*128];
        }
        g_Wg_h[i2] = __float2half_rn(w);
    } else if (idx < T3 + (size_t)NMAT*64*KP) {
        size_t i3 = idx - T3;
        int m = (int)(i3 / (64*KP));
        int rem = (int)(i3 - (size_t)m*(64*KP));
        int o = rem / KP, k = rem - o*KP;
        float w = 0.f;
        if (k < 66) {
            int f = (k < 64) ? (k + IND) : (k - 64);
            const float* base = Wc + (size_t)(f*NMAT)*64 + o;
            if      (m == 0) w = base[0] - base[2*64] - base[4*64];
            else if (m == 2) w = 2.f*base[2*64];
            else if (m == 4) w = 2.f*base[4*64];
            else             w = base[m*64];
        }
        g_Wc_h[i3] = __float2half_rn(w);
    }
}

// ---------------- SPMM: Y = A_m X (state rows + optional input rows) ---------
__device__ __forceinline__ void acc8(float* a, float w, uint4 h)
{
    float2 p0 = __half22float2(*(const __half2*)&h.x);
    float2 p1 = __half22float2(*(const __half2*)&h.y);
    float2 p2 = __half22float2(*(const __half2*)&h.z);
    float2 p3 = __half22float2(*(const __half2*)&h.w);
    a[0] += w*p0.x; a[1] += w*p0.y; a[2] += w*p1.x; a[3] += w*p1.y;
    a[4] += w*p2.x; a[5] += w*p2.y; a[6] += w*p3.x; a[7] += w*p3.y;
}
__device__ __forceinline__ uint4 pack8(const float* a)
{
    __half2 a0 = __floats2half2_rn(a[0],a[1]);
    __half2 a1 = __floats2half2_rn(a[2],a[3]);
    __half2 a2 = __floats2half2_rn(a[4],a[5]);
    __half2 a3 = __floats2half2_rn(a[6],a[7]);
    uint4 st; st.x=*(unsigned*)&a0; st.y=*(unsigned*)&a1; st.z=*(unsigned*)&a2; st.w=*(unsigned*)&a3;
    return st;
}

__global__ void __launch_bounds__(128) k_spmm(int xiA,int yiA,int xiB,int yiB)
{
    int m  = blockIdx.y;
    int xi = m ? xiB : xiA;
    int yi = m ? yiB : yiA;
    const int2* __restrict__ cw = g_cw[m];

    if (blockIdx.x < NN) {
        // ---- state row: 128 threads cover one 2048-B row ----
        const uint4* __restrict__ X = (const uint4*)(g_Xs + (size_t)xi*NN*SROW);
        uint4*       __restrict__ Y = (uint4*)      (g_Xs + (size_t)yi*NN*SROW);
        int r = blockIdx.x;
        int t = threadIdx.x;
        int beg = g_ptr[m][r], end = g_ptr[m][r+1];

        float acc[8] = {0.f,0.f,0.f,0.f,0.f,0.f,0.f,0.f};
        int j = beg;
        for (; j + 8 <= end; j += 8) {
            int2 e[8];
            #pragma unroll
            for (int u = 0; u < 8; u++) e[u] = __ldg(cw + j + u);
            uint4 h[8];
            #pragma unroll
            for (int u = 0; u < 8; u++) h[u] = __ldg(X + (size_t)e[u].x*SV4 + t);
            #pragma unroll
            for (int u = 0; u < 8; u++) acc8(acc, __int_as_float(e[u].y), h[u]);
        }
        for (; j < end; j++) {
            int2 e = __ldg(cw + j);
            uint4 h = __ldg(X + (size_t)e.x*SV4 + t);
            acc8(acc, __int_as_float(e.y), h);
        }
        Y[(size_t)r*SV4 + t] = pack8(acc);
    } else {
        // ---- input rows: 32 rows per block, 4 threads per 64-B row ----
        const uint4* __restrict__ X = (const uint4*)(g_Xin + (size_t)xi*NN*IROW);
        uint4*       __restrict__ Y = (uint4*)      (g_Xin + (size_t)yi*NN*IROW);
        int r = (blockIdx.x - NN)*32 + (threadIdx.x >> 2);
        int q = threadIdx.x & 3;
        int beg = g_ptr[m][r], end = g_ptr[m][r+1];
        float acc[8] = {0.f,0.f,0.f,0.f,0.f,0.f,0.f,0.f};
        for (int j = beg; j < end; j++) {
            int2 e = __ldg(cw + j);
            uint4 h = __ldg(X + (size_t)e.x*4 + q);
            acc8(acc, __int_as_float(e.y), h);
        }
        Y[(size_t)r*4 + q] = pack8(acc);
    }
}

// ---------------- MMA / ldmatrix helpers --------------------------------------
__device__ __forceinline__ void mma_16816(float c[4], const unsigned a[4], const unsigned b[2]) {
    asm volatile(
        "mma.sync.aligned.m16n8k16.row.col.f32.f16.f16.f32 "
        "{%0,%1,%2,%3},{%4,%5,%6,%7},{%8,%9},{%0,%1,%2,%3};\n"
        : "+f"(c[0]), "+f"(c[1]), "+f"(c[2]), "+f"(c[3])
        : "r"(a[0]), "r"(a[1]), "r"(a[2]), "r"(a[3]), "r"(b[0]), "r"(b[1]));
}
__device__ __forceinline__ void mma_1688(float c[4], const unsigned a[2], const unsigned b0) {
    asm volatile(
        "mma.sync.aligned.m16n8k8.row.col.f32.f16.f16.f32 "
        "{%0,%1,%2,%3},{%4,%5},{%6},{%0,%1,%2,%3};\n"
        : "+f"(c[0]), "+f"(c[1]), "+f"(c[2]), "+f"(c[3])
        : "r"(a[0]), "r"(a[1]), "r"(b0));
}
__device__ __forceinline__ unsigned su32(const void* p) {
    return (unsigned)__cvta_generic_to_shared(p);
}
__device__ __forceinline__ void ldsm4(unsigned* r, unsigned a) {
    asm volatile("ldmatrix.sync.aligned.m8n8.x4.shared.b16 {%0,%1,%2,%3},[%4];"
        : "=r"(r[0]),"=r"(r[1]),"=r"(r[2]),"=r"(r[3]) : "r"(a));
}
__device__ __forceinline__ void ldsm2(unsigned* r, unsigned a) {
    asm volatile("ldmatrix.sync.aligned.m8n8.x2.shared.b16 {%0,%1},[%2];"
        : "=r"(r[0]),"=r"(r[1]) : "r"(a));
}

// ---------------- gate GEMM (pipelined tile loads) + fused gating -------------
__global__ void __launch_bounds__(256) k_gemm_gate(const float* __restrict__ bg,
                                                   const float* __restrict__ state)
{
    __shared__ __align__(16) __half As[128][KP];
    __shared__ __align__(16) __half Bs[128][KP];

    int row0 = blockIdx.x * 128;
    int b  = row0 / NN;
    int n0 = row0 - b*NN;
    int tid = threadIdx.x;
    int wid = tid >> 5, lane = tid & 31;
    int q = lane & 3, rr_ = lane >> 2;
    int warp_m = wid & 3, warp_n = wid >> 2;

    unsigned Au[2], At[2], Bu[4], Bt[4];
    #pragma unroll
    for (int mt = 0; mt < 2; mt++) {
        Au[mt] = su32(&As[warp_m*32 + mt*16 + (lane & 15)][(lane >> 4)*8]);
        At[mt] = su32(&As[warp_m*32 + mt*16 + (lane & 15)][64]);
    }
    #pragma unroll
    for (int p = 0; p < 4; p++) {
        Bu[p] = su32(&Bs[warp_n*64 + p*16 + (lane & 7) + ((lane >> 4) & 1)*8][((lane >> 3) & 1)*8]);
        Bt[p] = su32(&Bs[warp_n*64 + p*16 + (lane & 7) + ((lane >> 3) & 1)*8][64]);
    }

    float acc[2][8][4];
    #pragma unroll
    for (int i = 0; i < 2; i++)
        #pragma unroll
        for (int j = 0; j < 8; j++)
            #pragma unroll
            for (int k = 0; k < 4; k++) acc[i][j][k] = 0.f;

    // prefetch registers: 9 uint4 per thread (A 1152 + B 1152 = 2304 = 256*9)
    uint4 rv[9];
    auto load_tile = [&](int m, uint4* rv_) {
        const uint4* Xs  = (const uint4*)(g_Xs + (size_t)m*NN*SROW);
        const __half* Xin = g_Xin + (size_t)m*NN*IROW;
        const __half* Wm  = g_Wg_h + m*128*KP;
        #pragma unroll
        for (int u = 0; u < 9; u++) {
            int idx = tid + u*256;
            if (idx < 1152) {
                int rrow = idx / 9, j = idx - rrow*9;
                uint4 v;
                if (j < 8) v = Xs[(size_t)(n0+rrow)*SV4 + b*8 + j];
                else { v.x = *(const unsigned*)(Xin + (size_t)(n0+rrow)*IROW + b*2);
                       v.y = 0u; v.z = 0u; v.w = 0u; }
                rv_[u] = v;
            } else {
                int i2 = idx - 1152;
                int o = i2 / 9, j = i2 - o*9;
                rv_[u] = *(const uint4*)(Wm + o*KP + 8*j);
            }
        }
    };

    load_tile(0, rv);
    for (int m = 0; m < NMAT; m++) {
        __syncthreads();
        #pragma unroll
        for (int u = 0; u < 9; u++) {
            int idx = tid + u*256;
            if (idx < 1152) { int rrow = idx / 9, j = idx - rrow*9;
                              ((uint4*)&As[rrow][0])[j] = rv[u]; }
            else            { int i2 = idx - 1152; int o = i2 / 9, j = i2 - o*9;
                              ((uint4*)&Bs[o][0])[j] = rv[u]; }
        }
        __syncthreads();
        if (m < NMAT-1) load_tile(m+1, rv);   // overlaps MMAs below

        #pragma unroll
        for (int ks = 0; ks < 4; ks++) {
            unsigned a0[4], a1[4];
            ldsm4(a0, Au[0] + ks*32);
            ldsm4(a1, Au[1] + ks*32);
            #pragma unroll
            for (int p = 0; p < 4; p++) {
                unsigned bb[4];
                ldsm4(bb, Bu[p] + ks*32);
                mma_16816(acc[0][2*p],   a0, bb);
                mma_16816(acc[0][2*p+1], a0, bb+2);
                mma_16816(acc[1][2*p],   a1, bb);
                mma_16816(acc[1][2*p+1], a1, bb+2);
            }
        }
        {
            unsigned a0[2], a1[2];
            ldsm2(a0, At[0]);
            ldsm2(a1, At[1]);
            #pragma unroll
            for (int p = 0; p < 4; p++) {
                unsigned bt[2];
                ldsm2(bt, Bt[p]);
                mma_1688(acc[0][2*p],   a0, bt[0]);
                mma_1688(acc[0][2*p+1], a0, bt[1]);
                mma_1688(acc[1][2*p],   a1, bt[0]);
                mma_1688(acc[1][2*p+1], a1, bt[1]);
            }
        }
    }

    __half* Xc0 = g_Xs + (size_t)5*NN*SROW;
    #pragma unroll
    for (int mt = 0; mt < 2; mt++) {
        #pragma unroll
        for (int nt = 0; nt < 8; nt++) {
            #pragma unroll
            for (int half_ : {0, 1}) {
                int row_l = warp_m*32 + mt*16 + rr_ + (half_ ? 8 : 0);
                int col   = warp_n*64 + nt*8 + 2*q;
                int n = n0 + row_l;
                float z0 = acc[mt][nt][2*half_+0] + bg[col];
                float z1 = acc[mt][nt][2*half_+1] + bg[col+1];
                float s0 = 1.f/(1.f + expf(-z0));
                float s1 = 1.f/(1.f + expf(-z1));
                if (col < HH) {
                    float2 st = *(const float2*)&state[(size_t)b*NN*HH + (size_t)n*HH + col];
                    __half2 rs = __floats2half2_rn(s0*st.x, s1*st.y);
                    *(__half2*)&Xc0[(size_t)n*SROW + b*HH + col] = rs;
                } else {
                    float2 u; u.x = s0; u.y = s1;
                    *(float2*)&g_U[(size_t)(row0+row_l)*HH + (col-HH)] = u;
                }
            }
        }
    }
}

// ---------------- candidate GEMM (pipelined) + GRU combine --------------------
__global__ void __launch_bounds__(256) k_gemm_cand(const float* __restrict__ bc,
                                                   const float* __restrict__ state,
                                                   float* __restrict__ out, int dup)
{
    __shared__ __align__(16) __half As[128][KP];
    __shared__ __align__(16) __half Bs[64][KP];

    int row0 = blockIdx.x * 128;
    int b  = row0 / NN;
    int n0 = row0 - b*NN;
    int tid = threadIdx.x;
    int wid = tid >> 5, lane = tid & 31;
    int q = lane & 3, rr_ = lane >> 2;
    int warp_m = wid & 3, warp_n = wid >> 2;

    unsigned Au[2], At[2], Bu[2], Bt[2];
    #pragma unroll
    for (int mt = 0; mt < 2; mt++) {
        Au[mt] = su32(&As[warp_m*32 + mt*16 + (lane & 15)][(lane >> 4)*8]);
        At[mt] = su32(&As[warp_m*32 + mt*16 + (lane & 15)][64]);
    }
    #pragma unroll
    for (int p = 0; p < 2; p++) {
        Bu[p] = su32(&Bs[warp_n*32 + p*16 + (lane & 7) + ((lane >> 4) & 1)*8][((lane >> 3) & 1)*8]);
        Bt[p] = su32(&Bs[warp_n*32 + p*16 + (lane & 7) + ((lane >> 3) & 1)*8][64]);
    }

    float acc[2][4][4];
    #pragma unroll
    for (int i = 0; i < 2; i++)
        #pragma unroll
        for (int j = 0; j < 4; j++)
            #pragma unroll
            for (int k = 0; k < 4; k++) acc[i][j][k] = 0.f;

    // A 1152 + B 576 = 1728 uint4 -> 7 per thread (guarded)
    uint4 rv[7];
    auto load_tile = [&](int m, uint4* rv_) {
        const uint4* Xs  = (const uint4*)(g_Xs + (size_t)(5+m)*NN*SROW);
        const __half* Xin = g_Xin + (size_t)m*NN*IROW;
        const __half* Wm  = g_Wc_h + m*64*KP;
        #pragma unroll
        for (int u = 0; u < 7; u++) {
            int idx = tid + u*256;
            if (idx < 1152) {
                int rrow = idx / 9, j = idx - rrow*9;
                uint4 v;
                if (j < 8) v = Xs[(size_t)(n0+rrow)*SV4 + b*8 + j];
                else { v.x = *(const unsigned*)(Xin + (size_t)(n0+rrow)*IROW + b*2);
                       v.y = 0u; v.z = 0u; v.w = 0u; }
                rv_[u] = v;
            } else if (idx < 1728) {
                int i2 = idx - 1152;
                int o = i2 / 9, j = i2 - o*9;
                rv_[u] = *(const uint4*)(Wm + o*KP + 8*j);
            }
        }
    };

    load_tile(0, rv);
    for (int m = 0; m < NMAT; m++) {
        __syncthreads();
        #pragma unroll
        for (int u = 0; u < 7; u++) {
            int idx = tid + u*256;
            if (idx < 1152) { int rrow = idx / 9, j = idx - rrow*9;
                              ((uint4*)&As[rrow][0])[j] = rv[u]; }
            else if (idx < 1728) { int i2 = idx - 1152; int o = i2 / 9, j = i2 - o*9;
                                   ((uint4*)&Bs[o][0])[j] = rv[u]; }
        }
        __syncthreads();
        if (m < NMAT-1) load_tile(m+1, rv);

        #pragma unroll
        for (int ks = 0; ks < 4; ks++) {
            unsigned a0[4], a1[4];
            ldsm4(a0, Au[0] + ks*32);
            ldsm4(a1, Au[1] + ks*32);
            #pragma unroll
            for (int p = 0; p < 2; p++) {
                unsigned bb[4];
                ldsm4(bb, Bu[p] + ks*32);
                mma_16816(acc[0][2*p],   a0, bb);
                mma_16816(acc[0][2*p+1], a0, bb+2);
                mma_16816(acc[1][2*p],   a1, bb);
                mma_16816(acc[1][2*p+1], a1, bb+2);
            }
        }
        {
            unsigned a0[2], a1[2];
            ldsm2(a0, At[0]);
            ldsm2(a1, At[1]);
            #pragma unroll
            for (int p = 0; p < 2; p++) {
                unsigned bt[2];
                ldsm2(bt, Bt[p]);
                mma_1688(acc[0][2*p],   a0, bt[0]);
                mma_1688(acc[0][2*p+1], a0, bt[1]);
                mma_1688(acc[1][2*p],   a1, bt[0]);
                mma_1688(acc[1][2*p+1], a1, bt[1]);
            }
        }
    }

    #pragma unroll
    for (int mt = 0; mt < 2; mt++) {
        #pragma unroll
        for (int nt = 0; nt < 4; nt++) {
            #pragma unroll
            for (int half_ : {0, 1}) {
                int row_l = warp_m*32 + mt*16 + rr_ + (half_ ? 8 : 0);
                int col   = warp_n*32 + nt*8 + 2*q;
                int n = n0 + row_l;
                int row = row0 + row_l;
                float c0 = tanhf(acc[mt][nt][2*half_+0] + bc[col]);
                float c1 = tanhf(acc[mt][nt][2*half_+1] + bc[col+1]);
                size_t sidx = (size_t)b*NN*HH + (size_t)n*HH + col;
                float2 u  = *(const float2*)&g_U[(size_t)row*HH + col];
                float2 st = *(const float2*)&state[sidx];
                float2 ns;
                ns.x = u.x*st.x + (1.f - u.x)*c0;
                ns.y = u.y*st.y + (1.f - u.y)*c1;
                *(float2*)&out[sidx] = ns;
                if (dup) *(float2*)&out[sidx + (size_t)BB*NN*HH] = ns;
            }
        }
    }
}

// ---------------- launch ------------------------------------------------------
extern "C" void kernel_launch(void* const* d_in, const int* in_sizes, int n_in,
                              void* d_out, int out_size)
{
    const float* inputs = (const float*)d_in[0];
    const float* state  = (const float*)d_in[1];
    const int*   esrc   = (const int*)  d_in[2];
    const int*   edst   = (const int*)  d_in[3];
    const float* v1     = (const float*)d_in[4];
    const float* v2     = (const float*)d_in[5];
    const float* Wg     = (const float*)d_in[6];
    const float* bg     = (const float*)d_in[7];
    const float* Wc     = (const float*)d_in[8];
    const float* bc     = (const float*)d_in[9];
    float* out = (float*)d_out;
    int dup = (out_size >= 2*BB*NN*HH) ? 1 : 0;

    void* p_cnt = nullptr; void* p_cur = nullptr;
    cudaGetSymbolAddress(&p_cnt, g_cnt);
    cudaGetSymbolAddress(&p_cur, g_cur);
    cudaMemsetAsync(p_cnt, 0, sizeof(int)*2*NN);
    cudaMemsetAsync(p_cur, 0, sizeof(int)*2*NN);

    k_count<<<EE/256, 256>>>(esrc, edst);
    k_scan<<<1, 1024>>>();
    k_scatter<<<EE/256, 256>>>(esrc, edst);
    k_sortfill<<<dim3(NN/256,2), 256>>>(esrc, edst, v1, v2);

    size_t init_total = (size_t)NN*SROW + (size_t)NN*IROW
                      + (size_t)NMAT*128*KP + (size_t)NMAT*64*KP;
    k_init<<<(unsigned)((init_total + 255)/256), 256>>>(inputs, state, Wg, Wc);

    // gate diffusion (state + input parts in one kernel):
    k_spmm<<<dim3(NN+INBLK,2), 128>>>(0,1, 0,3);
    k_spmm<<<dim3(NN+INBLK,2), 128>>>(1,2, 3,4);

    k_gemm_gate<<<(BB*NN)/128, 256>>>(bg, state);

    // candidate diffusion (state part only; input part shared):
    k_spmm<<<dim3(NN,2), 128>>>(5,6, 5,8);
    k_spmm<<<dim3(NN,2), 128>>>(6,7, 8,9);

    k_gemm_cand<<<(BB*NN)/128, 256>>>(bc, state, out, dup);
}

// round 7
// speedup vs baseline: 2.9272x; 1.0614x over previous
#include <cuda_runtime.h>
#include <cuda_fp16.h>
#include <math.h>

#define NN   8192
#define BB   16
#define IND  2
#define HH   64
#define FF   66
#define EE   131072
#define NMAT 5
#define KP   72
#define SROW 1024     // 16 batches * 64 halves = 2048 B
#define SV4  128      // uint4 per state row
#define IROW 32       // 16 batches * 2 halves = 64 B
#define INBLK (NN/32) // input-part blocks (32 rows per 128-thread block)

// ---------------- device scratch (static) ------------------------------------
__device__ __half g_Xs[(size_t)10*NN*SROW];
__device__ __half g_Xin[(size_t)5*NN*IROW];
__device__ float  g_U[(size_t)BB*NN*HH];
__device__ __half g_Wg_h[NMAT*128*KP];
__device__ __half g_Wc_h[NMAT*64*KP];
__device__ int   g_cnt[2][NN];
__device__ int   g_cur[2][NN];
__device__ int   g_ptr[2][NN+1];
__device__ int   g_eidx[2][EE];
__device__ int2  g_cw[2][EE];

// ---------------- CSR build (deterministic) ----------------------------------
__global__ void k_count(const int* __restrict__ src, const int* __restrict__ dst)
{
    int e4 = blockIdx.x*blockDim.x + threadIdx.x;
    if (e4 < EE/4) {
        int4 s = __ldg((const int4*)src + e4);
        int4 d = __ldg((const int4*)dst + e4);
        atomicAdd(&g_cnt[0][s.x], 1); atomicAdd(&g_cnt[0][s.y], 1);
        atomicAdd(&g_cnt[0][s.z], 1); atomicAdd(&g_cnt[0][s.w], 1);
        atomicAdd(&g_cnt[1][d.x], 1); atomicAdd(&g_cnt[1][d.y], 1);
        atomicAdd(&g_cnt[1][d.z], 1); atomicAdd(&g_cnt[1][d.w], 1);
    }
}

__global__ void k_scan()
{
    __shared__ int wsum[32];
    int tid = threadIdx.x, lane = tid & 31, wrp = tid >> 5;
    for (int m = 0; m < 2; m++) {
        int base = tid*8;
        int c[8];
        int s_local = 0;
        #pragma unroll
        for (int j = 0; j < 8; j++) { c[j] = g_cnt[m][base+j]; s_local += c[j]; }
        int v = s_local;
        #pragma unroll
        for (int off = 1; off < 32; off <<= 1) {
            int o = __shfl_up_sync(0xffffffffu, v, off);
            if (lane >= off) v += o;
        }
        if (lane == 31) wsum[wrp] = v;
        __syncthreads();
        if (wrp == 0) {
            int w = wsum[lane];
            #pragma unroll
            for (int off = 1; off < 32; off <<= 1) {
                int o = __shfl_up_sync(0xffffffffu, w, off);
                if (lane >= off) w += o;
            }
            wsum[lane] = w;
        }
        __syncthreads();
        int run = v - s_local + (wrp ? wsum[wrp-1] : 0);
        #pragma unroll
        for (int j = 0; j < 8; j++) { g_ptr[m][base+j] = run; run += c[j]; }
        if (tid == 1023) g_ptr[m][NN] = run;
        __syncthreads();
    }
}

__global__ void k_scatter(const int* __restrict__ src, const int* __restrict__ dst)
{
    int e = blockIdx.x*blockDim.x + threadIdx.x;
    if (e < EE) {
        int r = src[e];
        int p = g_ptr[0][r] + atomicAdd(&g_cur[0][r], 1);
        g_eidx[0][p] = e;
        r = dst[e];
        p = g_ptr[1][r] + atomicAdd(&g_cur[1][r], 1);
        g_eidx[1][p] = e;
    }
}

// ---- warp-per-row bitonic sort (64 elems, 2 per lane) + fill -----------------
__global__ void k_sortfill(const int* __restrict__ src, const int* __restrict__ dst,
                           const float* __restrict__ v1, const float* __restrict__ v2)
{
    int m    = blockIdx.y;
    int wrp  = threadIdx.x >> 5;
    int lane = threadIdx.x & 31;
    int r    = blockIdx.x*8 + wrp;
    if (r >= NN) return;
    int beg = g_ptr[m][r], end = g_ptr[m][r+1];
    int deg = end - beg;

    if (deg <= 64) {
        const int BIG = 0x7fffffff;
        int e0 = (lane      < deg) ? g_eidx[m][beg + lane]      : BIG;
        int e1 = (lane + 32 < deg) ? g_eidx[m][beg + lane + 32] : BIG;

        #pragma unroll
        for (int k = 2; k <= 64; k <<= 1) {
            #pragma unroll
            for (int j = k >> 1; j > 0; j >>= 1) {
                if (j == 32) {
                    // partner across halves (index i <-> i^32): in-thread
                    int lo = min(e0, e1), hi = max(e0, e1);
                    e0 = lo; e1 = hi;      // k==64 only: ascending everywhere
                } else {
                    int p0 = __shfl_xor_sync(0xffffffffu, e0, j);
                    bool up0 = ((lane & k) == 0) || (k == 64);
                    bool km0 = (((lane & j) == 0) == up0);
                    e0 = km0 ? min(e0, p0) : max(e0, p0);
                    int p1 = __shfl_xor_sync(0xffffffffu, e1, j);
                    bool up1 = (k == 64) || (((lane + 32) & k) == 0);
                    bool km1 = (((lane & j) == 0) == up1);
                    e1 = km1 ? min(e1, p1) : max(e1, p1);
                }
            }
        }
        // write back sorted; pads (BIG) land at positions >= deg
        if (lane < deg) {
            int e = e0;
            int2 cw;
            if (m == 0) { cw.x = __ldg(dst+e); cw.y = __float_as_int(__ldg(v1+e)); }
            else        { cw.x = __ldg(src+e); cw.y = __float_as_int(__ldg(v2+e)); }
            g_cw[m][beg + lane] = cw;
        }
        if (lane + 32 < deg) {
            int e = e1;
            int2 cw;
            if (m == 0) { cw.x = __ldg(dst+e); cw.y = __float_as_int(__ldg(v1+e)); }
            else        { cw.x = __ldg(src+e); cw.y = __float_as_int(__ldg(v2+e)); }
            g_cw[m][beg + lane + 32] = cw;
        }
    } else if (lane == 0) {
        // rare fallback: serial insertion sort
        for (int i = beg+1; i < end; i++) {
            int key = g_eidx[m][i];
            int j = i-1;
            while (j >= beg && g_eidx[m][j] > key) { g_eidx[m][j+1] = g_eidx[m][j]; j--; }
            g_eidx[m][j+1] = key;
        }
        for (int i = beg; i < end; i++) {
            int e = g_eidx[m][i];
            int2 cw;
            if (m == 0) { cw.x = dst[e]; cw.y = __float_as_int(v1[e]); }
            else        { cw.x = src[e]; cw.y = __float_as_int(v2[e]); }
            g_cw[m][i] = cw;
        }
    }
}

// ---------------- init: Xs0, Xin0, folded+permuted weights -------------------
__global__ void k_init(const float* __restrict__ inputs, const float* __restrict__ state,
                       const float* __restrict__ Wg, const float* __restrict__ Wc)
{
    const size_t T1 = (size_t)NN*SROW;
    const size_t T2 = T1 + (size_t)NN*IROW;
    const size_t T3 = T2 + (size_t)NMAT*128*KP;
    size_t idx = (size_t)blockIdx.x*blockDim.x + threadIdx.x;
    if (idx < T1) {
        int n = (int)(idx / SROW);
        int c = (int)(idx - (size_t)n*SROW);
        int b = c >> 6, h = c & 63;
        g_Xs[idx] = __float2half_rn(state[(size_t)b*NN*HH + (size_t)n*HH + h]);
    } else if (idx < T2) {
        size_t i1 = idx - T1;
        int n = (int)(i1 / IROW);
        int c = (int)(i1 - (size_t)n*IROW);
        int b = c >> 1, j = c & 1;
        g_Xin[i1] = __float2half_rn(inputs[(size_t)b*NN*IND + (size_t)n*IND + j]);
    } else if (idx < T3) {
        size_t i2 = idx - T2;
        int m = (int)(i2 / (128*KP));
        int rem = (int)(i2 - (size_t)m*(128*KP));
        int o = rem / KP, k = rem - o*KP;
        float w = 0.f;
        if (k < 66) {
            int f = (k < 64) ? (k + IND) : (k - 64);
            const float* base = Wg + (size_t)(f*NMAT)*128 + o;
            if      (m == 0) w = base[0] - base[2*128] - base[4*128];
            else if (m == 2) w = 2.f*base[2*128];
            else if (m == 4) w = 2.f*base[4*128];
            else             w = base[m*128];
        }
        g_Wg_h[i2] = __float2half_rn(w);
    } else if (idx < T3 + (size_t)NMAT*64*KP) {
        size_t i3 = idx - T3;
        int m = (int)(i3 / (64*KP));
        int rem = (int)(i3 - (size_t)m*(64*KP));
        int o = rem / KP, k = rem - o*KP;
        float w = 0.f;
        if (k < 66) {
            int f = (k < 64) ? (k + IND) : (k - 64);
            const float* base = Wc + (size_t)(f*NMAT)*64 + o;
            if      (m == 0) w = base[0] - base[2*64] - base[4*64];
            else if (m == 2) w = 2.f*base[2*64];
            else if (m == 4) w = 2.f*base[4*64];
            else             w = base[m*64];
        }
        g_Wc_h[i3] = __float2half_rn(w);
    }
}

// ---------------- SPMM: Y = A_m X (state rows + optional input rows) ---------
__device__ __forceinline__ void acc8(float* a, float w, uint4 h)
{
    float2 p0 = __half22float2(*(const __half2*)&h.x);
    float2 p1 = __half22float2(*(const __half2*)&h.y);
    float2 p2 = __half22float2(*(const __half2*)&h.z);
    float2 p3 = __half22float2(*(const __half2*)&h.w);
    a[0] += w*p0.x; a[1] += w*p0.y; a[2] += w*p1.x; a[3] += w*p1.y;
    a[4] += w*p2.x; a[5] += w*p2.y; a[6] += w*p3.x; a[7] += w*p3.y;
}
__device__ __forceinline__ uint4 pack8(const float* a)
{
    __half2 a0 = __floats2half2_rn(a[0],a[1]);
    __half2 a1 = __floats2half2_rn(a[2],a[3]);
    __half2 a2 = __floats2half2_rn(a[4],a[5]);
    __half2 a3 = __floats2half2_rn(a[6],a[7]);
    uint4 st; st.x=*(unsigned*)&a0; st.y=*(unsigned*)&a1; st.z=*(unsigned*)&a2; st.w=*(unsigned*)&a3;
    return st;
}

__global__ void __launch_bounds__(128) k_spmm(int xiA,int yiA,int xiB,int yiB)
{
    int m  = blockIdx.y;
    int xi = m ? xiB : xiA;
    int yi = m ? yiB : yiA;
    const int2* __restrict__ cw = g_cw[m];

    if (blockIdx.x < NN) {
        const uint4* __restrict__ X = (const uint4*)(g_Xs + (size_t)xi*NN*SROW);
        uint4*       __restrict__ Y = (uint4*)      (g_Xs + (size_t)yi*NN*SROW);
        int r = blockIdx.x;
        int t = threadIdx.x;
        int beg = g_ptr[m][r], end = g_ptr[m][r+1];

        float acc[8] = {0.f,0.f,0.f,0.f,0.f,0.f,0.f,0.f};
        int j = beg;
        for (; j + 8 <= end; j += 8) {
            int2 e[8];
            #pragma unroll
            for (int u = 0; u < 8; u++) e[u] = __ldg(cw + j + u);
            uint4 h[8];
            #pragma unroll
            for (int u = 0; u < 8; u++) h[u] = __ldg(X + (size_t)e[u].x*SV4 + t);
            #pragma unroll
            for (int u = 0; u < 8; u++) acc8(acc, __int_as_float(e[u].y), h[u]);
        }
        for (; j < end; j++) {
            int2 e = __ldg(cw + j);
            uint4 h = __ldg(X + (size_t)e.x*SV4 + t);
            acc8(acc, __int_as_float(e.y), h);
        }
        Y[(size_t)r*SV4 + t] = pack8(acc);
    } else {
        const uint4* __restrict__ X = (const uint4*)(g_Xin + (size_t)xi*NN*IROW);
        uint4*       __restrict__ Y = (uint4*)      (g_Xin + (size_t)yi*NN*IROW);
        int r = (blockIdx.x - NN)*32 + (threadIdx.x >> 2);
        int q = threadIdx.x & 3;
        int beg = g_ptr[m][r], end = g_ptr[m][r+1];
        float acc[8] = {0.f,0.f,0.f,0.f,0.f,0.f,0.f,0.f};
        for (int j = beg; j < end; j++) {
            int2 e = __ldg(cw + j);
            uint4 h = __ldg(X + (size_t)e.x*4 + q);
            acc8(acc, __int_as_float(e.y), h);
        }
        Y[(size_t)r*4 + q] = pack8(acc);
    }
}

// ---------------- MMA / ldmatrix helpers --------------------------------------
__device__ __forceinline__ void mma_16816(float c[4], const unsigned a[4], const unsigned b[2]) {
    asm volatile(
        "mma.sync.aligned.m16n8k16.row.col.f32.f16.f16.f32 "
        "{%0,%1,%2,%3},{%4,%5,%6,%7},{%8,%9},{%0,%1,%2,%3};\n"
        : "+f"(c[0]), "+f"(c[1]), "+f"(c[2]), "+f"(c[3])
        : "r"(a[0]), "r"(a[1]), "r"(a[2]), "r"(a[3]), "r"(b[0]), "r"(b[1]));
}
__device__ __forceinline__ void mma_1688(float c[4], const unsigned a[2], const unsigned b0) {
    asm volatile(
        "mma.sync.aligned.m16n8k8.row.col.f32.f16.f16.f32 "
        "{%0,%1,%2,%3},{%4,%5},{%6},{%0,%1,%2,%3};\n"
        : "+f"(c[0]), "+f"(c[1]), "+f"(c[2]), "+f"(c[3])
        : "r"(a[0]), "r"(a[1]), "r"(b0));
}
__device__ __forceinline__ unsigned su32(const void* p) {
    return (unsigned)__cvta_generic_to_shared(p);
}
__device__ __forceinline__ void ldsm4(unsigned* r, unsigned a) {
    asm volatile("ldmatrix.sync.aligned.m8n8.x4.shared.b16 {%0,%1,%2,%3},[%4];"
        : "=r"(r[0]),"=r"(r[1]),"=r"(r[2]),"=r"(r[3]) : "r"(a));
}
__device__ __forceinline__ void ldsm2(unsigned* r, unsigned a) {
    asm volatile("ldmatrix.sync.aligned.m8n8.x2.shared.b16 {%0,%1},[%2];"
        : "=r"(r[0]),"=r"(r[1]) : "r"(a));
}

// ---------------- gate GEMM (pipelined tile loads) + fused gating -------------
__global__ void __launch_bounds__(256) k_gemm_gate(const float* __restrict__ bg,
                                                   const float* __restrict__ state)
{
    __shared__ __align__(16) __half As[128][KP];
    __shared__ __align__(16) __half Bs[128][KP];

    int row0 = blockIdx.x * 128;
    int b  = row0 / NN;
    int n0 = row0 - b*NN;
    int tid = threadIdx.x;
    int wid = tid >> 5, lane = tid & 31;
    int q = lane & 3, rr_ = lane >> 2;
    int warp_m = wid & 3, warp_n = wid >> 2;

    unsigned Au[2], At[2], Bu[4], Bt[4];
    #pragma unroll
    for (int mt = 0; mt < 2; mt++) {
        Au[mt] = su32(&As[warp_m*32 + mt*16 + (lane & 15)][(lane >> 4)*8]);
        At[mt] = su32(&As[warp_m*32 + mt*16 + (lane & 15)][64]);
    }
    #pragma unroll
    for (int p = 0; p < 4; p++) {
        Bu[p] = su32(&Bs[warp_n*64 + p*16 + (lane & 7) + ((lane >> 4) & 1)*8][((lane >> 3) & 1)*8]);
        Bt[p] = su32(&Bs[warp_n*64 + p*16 + (lane & 7) + ((lane >> 3) & 1)*8][64]);
    }

    float acc[2][8][4];
    #pragma unroll
    for (int i = 0; i < 2; i++)
        #pragma unroll
        for (int j = 0; j < 8; j++)
            #pragma unroll
            for (int k = 0; k < 4; k++) acc[i][j][k] = 0.f;

    uint4 rv[9];
    auto load_tile = [&](int m, uint4* rv_) {
        const uint4* Xs  = (const uint4*)(g_Xs + (size_t)m*NN*SROW);
        const __half* Xin = g_Xin + (size_t)m*NN*IROW;
        const __half* Wm  = g_Wg_h + m*128*KP;
        #pragma unroll
        for (int u = 0; u < 9; u++) {
            int idx = tid + u*256;
            if (idx < 1152) {
                int rrow = idx / 9, j = idx - rrow*9;
                uint4 v;
                if (j < 8) v = Xs[(size_t)(n0+rrow)*SV4 + b*8 + j];
                else { v.x = *(const unsigned*)(Xin + (size_t)(n0+rrow)*IROW + b*2);
                       v.y = 0u; v.z = 0u; v.w = 0u; }
                rv_[u] = v;
            } else {
                int i2 = idx - 1152;
                int o = i2 / 9, j = i2 - o*9;
                rv_[u] = *(const uint4*)(Wm + o*KP + 8*j);
            }
        }
    };

    load_tile(0, rv);
    for (int m = 0; m < NMAT; m++) {
        __syncthreads();
        #pragma unroll
        for (int u = 0; u < 9; u++) {
            int idx = tid + u*256;
            if (idx < 1152) { int rrow = idx / 9, j = idx - rrow*9;
                              ((uint4*)&As[rrow][0])[j] = rv[u]; }
            else            { int i2 = idx - 1152; int o = i2 / 9, j = i2 - o*9;
                              ((uint4*)&Bs[o][0])[j] = rv[u]; }
        }
        __syncthreads();
        if (m < NMAT-1) load_tile(m+1, rv);

        #pragma unroll
        for (int ks = 0; ks < 4; ks++) {
            unsigned a0[4], a1[4];
            ldsm4(a0, Au[0] + ks*32);
            ldsm4(a1, Au[1] + ks*32);
            #pragma unroll
            for (int p = 0; p < 4; p++) {
                unsigned bb[4];
                ldsm4(bb, Bu[p] + ks*32);
                mma_16816(acc[0][2*p],   a0, bb);
                mma_16816(acc[0][2*p+1], a0, bb+2);
                mma_16816(acc[1][2*p],   a1, bb);
                mma_16816(acc[1][2*p+1], a1, bb+2);
            }
        }
        {
            unsigned a0[2], a1[2];
            ldsm2(a0, At[0]);
            ldsm2(a1, At[1]);
            #pragma unroll
            for (int p = 0; p < 4; p++) {
                unsigned bt[2];
                ldsm2(bt, Bt[p]);
                mma_1688(acc[0][2*p],   a0, bt[0]);
                mma_1688(acc[0][2*p+1], a0, bt[1]);
                mma_1688(acc[1][2*p],   a1, bt[0]);
                mma_1688(acc[1][2*p+1], a1, bt[1]);
            }
        }
    }

    __half* Xc0 = g_Xs + (size_t)5*NN*SROW;
    #pragma unroll
    for (int mt = 0; mt < 2; mt++) {
        #pragma unroll
        for (int nt = 0; nt < 8; nt++) {
            #pragma unroll
            for (int half_ : {0, 1}) {
                int row_l = warp_m*32 + mt*16 + rr_ + (half_ ? 8 : 0);
                int col   = warp_n*64 + nt*8 + 2*q;
                int n = n0 + row_l;
                float z0 = acc[mt][nt][2*half_+0] + bg[col];
                float z1 = acc[mt][nt][2*half_+1] + bg[col+1];
                float s0 = 1.f/(1.f + expf(-z0));
                float s1 = 1.f/(1.f + expf(-z1));
                if (col < HH) {
                    float2 st = *(const float2*)&state[(size_t)b*NN*HH + (size_t)n*HH + col];
                    __half2 rs = __floats2half2_rn(s0*st.x, s1*st.y);
                    *(__half2*)&Xc0[(size_t)n*SROW + b*HH + col] = rs;
                } else {
                    float2 u; u.x = s0; u.y = s1;
                    *(float2*)&g_U[(size_t)(row0+row_l)*HH + (col-HH)] = u;
                }
            }
        }
    }
}

// ---------------- candidate GEMM (pipelined) + GRU combine --------------------
__global__ void __launch_bounds__(256) k_gemm_cand(const float* __restrict__ bc,
                                                   const float* __restrict__ state,
                                                   float* __restrict__ out, int dup)
{
    __shared__ __align__(16) __half As[128][KP];
    __shared__ __align__(16) __half Bs[64][KP];

    int row0 = blockIdx.x * 128;
    int b  = row0 / NN;
    int n0 = row0 - b*NN;
    int tid = threadIdx.x;
    int wid = tid >> 5, lane = tid & 31;
    int q = lane & 3, rr_ = lane >> 2;
    int warp_m = wid & 3, warp_n = wid >> 2;

    unsigned Au[2], At[2], Bu[2], Bt[2];
    #pragma unroll
    for (int mt = 0; mt < 2; mt++) {
        Au[mt] = su32(&As[warp_m*32 + mt*16 + (lane & 15)][(lane >> 4)*8]);
        At[mt] = su32(&As[warp_m*32 + mt*16 + (lane & 15)][64]);
    }
    #pragma unroll
    for (int p = 0; p < 2; p++) {
        Bu[p] = su32(&Bs[warp_n*32 + p*16 + (lane & 7) + ((lane >> 4) & 1)*8][((lane >> 3) & 1)*8]);
        Bt[p] = su32(&Bs[warp_n*32 + p*16 + (lane & 7) + ((lane >> 3) & 1)*8][64]);
    }

    float acc[2][4][4];
    #pragma unroll
    for (int i = 0; i < 2; i++)
        #pragma unroll
        for (int j = 0; j < 4; j++)
            #pragma unroll
            for (int k = 0; k < 4; k++) acc[i][j][k] = 0.f;

    uint4 rv[7];
    auto load_tile = [&](int m, uint4* rv_) {
        const uint4* Xs  = (const uint4*)(g_Xs + (size_t)(5+m)*NN*SROW);
        const __half* Xin = g_Xin + (size_t)m*NN*IROW;
        const __half* Wm  = g_Wc_h + m*64*KP;
        #pragma unroll
        for (int u = 0; u < 7; u++) {
            int idx = tid + u*256;
            if (idx < 1152) {
                int rrow = idx / 9, j = idx - rrow*9;
                uint4 v;
                if (j < 8) v = Xs[(size_t)(n0+rrow)*SV4 + b*8 + j];
                else { v.x = *(const unsigned*)(Xin + (size_t)(n0+rrow)*IROW + b*2);
                       v.y = 0u; v.z = 0u; v.w = 0u; }
                rv_[u] = v;
            } else if (idx < 1728) {
                int i2 = idx - 1152;
                int o = i2 / 9, j = i2 - o*9;
                rv_[u] = *(const uint4*)(Wm + o*KP + 8*j);
            }
        }
    };

    load_tile(0, rv);
    for (int m = 0; m < NMAT; m++) {
        __syncthreads();
        #pragma unroll
        for (int u = 0; u < 7; u++) {
            int idx = tid + u*256;
            if (idx < 1152) { int rrow = idx / 9, j = idx - rrow*9;
                              ((uint4*)&As[rrow][0])[j] = rv[u]; }
            else if (idx < 1728) { int i2 = idx - 1152; int o = i2 / 9, j = i2 - o*9;
                                   ((uint4*)&Bs[o][0])[j] = rv[u]; }
        }
        __syncthreads();
        if (m < NMAT-1) load_tile(m+1, rv);

        #pragma unroll
        for (int ks = 0; ks < 4; ks++) {
            unsigned a0[4], a1[4];
            ldsm4(a0, Au[0] + ks*32);
            ldsm4(a1, Au[1] + ks*32);
            #pragma unroll
            for (int p = 0; p < 2; p++) {
                unsigned bb[4];
                ldsm4(bb, Bu[p] + ks*32);
                mma_16816(acc[0][2*p],   a0, bb);
                mma_16816(acc[0][2*p+1], a0, bb+2);
                mma_16816(acc[1][2*p],   a1, bb);
                mma_16816(acc[1][2*p+1], a1, bb+2);
            }
        }
        {
            unsigned a0[2], a1[2];
            ldsm2(a0, At[0]);
            ldsm2(a1, At[1]);
            #pragma unroll
            for (int p = 0; p < 2; p++) {
                unsigned bt[2];
                ldsm2(bt, Bt[p]);
                mma_1688(acc[0][2*p],   a0, bt[0]);
                mma_1688(acc[0][2*p+1], a0, bt[1]);
                mma_1688(acc[1][2*p],   a1, bt[0]);
                mma_1688(acc[1][2*p+1], a1, bt[1]);
            }
        }
    }

    #pragma unroll
    for (int mt = 0; mt < 2; mt++) {
        #pragma unroll
        for (int nt = 0; nt < 4; nt++) {
            #pragma unroll
            for (int half_ : {0, 1}) {
                int row_l = warp_m*32 + mt*16 + rr_ + (half_ ? 8 : 0);
                int col   = warp_n*32 + nt*8 + 2*q;
                int n = n0 + row_l;
                int row = row0 + row_l;
                float c0 = tanhf(acc[mt][nt][2*half_+0] + bc[col]);
                float c1 = tanhf(acc[mt][nt][2*half_+1] + bc[col+1]);
                size_t sidx = (size_t)b*NN*HH + (size_t)n*HH + col;
                float2 u  = *(const float2*)&g_U[(size_t)row*HH + col];
                float2 st = *(const float2*)&state[sidx];
                float2 ns;
                ns.x = u.x*st.x + (1.f - u.x)*c0;
                ns.y = u.y*st.y + (1.f - u.y)*c1;
                *(float2*)&out[sidx] = ns;
                if (dup) *(float2*)&out[sidx + (size_t)BB*NN*HH] = ns;
            }
        }
    }
}

// ---------------- launch ------------------------------------------------------
extern "C" void kernel_launch(void* const* d_in, const int* in_sizes, int n_in,
                              void* d_out, int out_size)
{
    const float* inputs = (const float*)d_in[0];
    const float* state  = (const float*)d_in[1];
    const int*   esrc   = (const int*)  d_in[2];
    const int*   edst   = (const int*)  d_in[3];
    const float* v1     = (const float*)d_in[4];
    const float* v2     = (const float*)d_in[5];
    const float* Wg     = (const float*)d_in[6];
    const float* bg     = (const float*)d_in[7];
    const float* Wc     = (const float*)d_in[8];
    const float* bc     = (const float*)d_in[9];
    float* out = (float*)d_out;
    int dup = (out_size >= 2*BB*NN*HH) ? 1 : 0;

    void* p_cnt = nullptr; void* p_cur = nullptr;
    cudaGetSymbolAddress(&p_cnt, g_cnt);
    cudaGetSymbolAddress(&p_cur, g_cur);
    cudaMemsetAsync(p_cnt, 0, sizeof(int)*2*NN);
    cudaMemsetAsync(p_cur, 0, sizeof(int)*2*NN);

    k_count<<<EE/4/256, 256>>>(esrc, edst);
    k_scan<<<1, 1024>>>();
    k_scatter<<<EE/256, 256>>>(esrc, edst);
    k_sortfill<<<dim3(NN/8,2), 256>>>(esrc, edst, v1, v2);

    size_t init_total = (size_t)NN*SROW + (size_t)NN*IROW
                      + (size_t)NMAT*128*KP + (size_t)NMAT*64*KP;
    k_init<<<(unsigned)((init_total + 255)/256), 256>>>(inputs, state, Wg, Wc);

    k_spmm<<<dim3(NN+INBLK,2), 128>>>(0,1, 0,3);
    k_spmm<<<dim3(NN+INBLK,2), 128>>>(1,2, 3,4);

    k_gemm_gate<<<(BB*NN)/128, 256>>>(bg, state);

    k_spmm<<<dim3(NN,2), 128>>>(5,6, 5,8);
    k_spmm<<<dim3(NN,2), 128>>>(6,7, 8,9);

    k_gemm_cand<<<(BB*NN)/128, 256>>>(bc, state, out, dup);
}

// round 8
// speedup vs baseline: 3.0173x; 1.0308x over previous
#include <cuda_runtime.h>
#include <cuda_fp16.h>
#include <math.h>

#define NN   8192
#define BB   16
#define IND  2
#define HH   64
#define FF   66
#define EE   131072
#define NMAT 5
#define KP   72
#define SROW 1024     // 16 batches * 64 halves = 2048 B
#define SV4  128      // uint4 per state row
#define IROW 32       // 16 batches * 2 halves = 64 B
#define INBLK (NN/32) // input-part spmm blocks
#define CNT_BLKS (EE/4/256)                 // 128
#define INIT_TOTAL ((size_t)NN*SROW + (size_t)NN*IROW + (size_t)NMAT*128*KP + (size_t)NMAT*64*KP)
#define INIT_BLKS ((unsigned)((INIT_TOTAL + 255)/256))

// ---------------- device scratch (static; zero-initialized at load) ----------
__device__ __half g_Xs[(size_t)10*NN*SROW];
__device__ __half g_Xin[(size_t)5*NN*IROW];
__device__ __half g_U[(size_t)BB*NN*HH];
__device__ __half g_Wg_h[NMAT*128*KP];
__device__ __half g_Wc_h[NMAT*64*KP];
__device__ int   g_cnt[2][NN];     // zeroed by k_sortfill each call
__device__ int   g_cur[2][NN];     // zeroed by k_sortfill each call
__device__ int   g_ptr[2][NN+1];
__device__ int   g_eidx[2][EE];
__device__ int2  g_cw[2][EE];

// ---------------- fused count + init -----------------------------------------
__global__ void k_count_init(const int* __restrict__ src, const int* __restrict__ dst,
                             const float* __restrict__ inputs, const float* __restrict__ state,
                             const float* __restrict__ Wg, const float* __restrict__ Wc)
{
    if (blockIdx.x < CNT_BLKS) {
        int e4 = blockIdx.x*blockDim.x + threadIdx.x;
        int4 s = __ldg((const int4*)src + e4);
        int4 d = __ldg((const int4*)dst + e4);
        atomicAdd(&g_cnt[0][s.x], 1); atomicAdd(&g_cnt[0][s.y], 1);
        atomicAdd(&g_cnt[0][s.z], 1); atomicAdd(&g_cnt[0][s.w], 1);
        atomicAdd(&g_cnt[1][d.x], 1); atomicAdd(&g_cnt[1][d.y], 1);
        atomicAdd(&g_cnt[1][d.z], 1); atomicAdd(&g_cnt[1][d.w], 1);
        return;
    }
    const size_t T1 = (size_t)NN*SROW;
    const size_t T2 = T1 + (size_t)NN*IROW;
    const size_t T3 = T2 + (size_t)NMAT*128*KP;
    size_t idx = (size_t)(blockIdx.x - CNT_BLKS)*blockDim.x + threadIdx.x;
    if (idx < T1) {
        int n = (int)(idx / SROW);
        int c = (int)(idx - (size_t)n*SROW);
        int b = c >> 6, h = c & 63;
        g_Xs[idx] = __float2half_rn(state[(size_t)b*NN*HH + (size_t)n*HH + h]);
    } else if (idx < T2) {
        size_t i1 = idx - T1;
        int n = (int)(i1 / IROW);
        int c = (int)(i1 - (size_t)n*IROW);
        int b = c >> 1, j = c & 1;
        g_Xin[i1] = __float2half_rn(inputs[(size_t)b*NN*IND + (size_t)n*IND + j]);
    } else if (idx < T3) {
        size_t i2 = idx - T2;
        int m = (int)(i2 / (128*KP));
        int rem = (int)(i2 - (size_t)m*(128*KP));
        int o = rem / KP, k = rem - o*KP;
        float w = 0.f;
        if (k < 66) {
            int f = (k < 64) ? (k + IND) : (k - 64);
            const float* base = Wg + (size_t)(f*NMAT)*128 + o;
            if      (m == 0) w = base[0] - base[2*128] - base[4*128];
            else if (m == 2) w = 2.f*base[2*128];
            else if (m == 4) w = 2.f*base[4*128];
            else             w = base[m*128];
        }
        g_Wg_h[i2] = __float2half_rn(w);
    } else if (idx < INIT_TOTAL) {
        size_t i3 = idx - T3;
        int m = (int)(i3 / (64*KP));
        int rem = (int)(i3 - (size_t)m*(64*KP));
        int o = rem / KP, k = rem - o*KP;
        float w = 0.f;
        if (k < 66) {
            int f = (k < 64) ? (k + IND) : (k - 64);
            const float* base = Wc + (size_t)(f*NMAT)*64 + o;
            if      (m == 0) w = base[0] - base[2*64] - base[4*64];
            else if (m == 2) w = 2.f*base[2*64];
            else if (m == 4) w = 2.f*base[4*64];
            else             w = base[m*64];
        }
        g_Wc_h[i3] = __float2half_rn(w);
    }
}

__global__ void k_scan()
{
    __shared__ int wsum[32];
    int tid = threadIdx.x, lane = tid & 31, wrp = tid >> 5;
    for (int m = 0; m < 2; m++) {
        int base = tid*8;
        int c[8];
        int s_local = 0;
        #pragma unroll
        for (int j = 0; j < 8; j++) { c[j] = g_cnt[m][base+j]; s_local += c[j]; }
        int v = s_local;
        #pragma unroll
        for (int off = 1; off < 32; off <<= 1) {
            int o = __shfl_up_sync(0xffffffffu, v, off);
            if (lane >= off) v += o;
        }
        if (lane == 31) wsum[wrp] = v;
        __syncthreads();
        if (wrp == 0) {
            int w = wsum[lane];
            #pragma unroll
            for (int off = 1; off < 32; off <<= 1) {
                int o = __shfl_up_sync(0xffffffffu, w, off);
                if (lane >= off) w += o;
            }
            wsum[lane] = w;
        }
        __syncthreads();
        int run = v - s_local + (wrp ? wsum[wrp-1] : 0);
        #pragma unroll
        for (int j = 0; j < 8; j++) { g_ptr[m][base+j] = run; run += c[j]; }
        if (tid == 1023) g_ptr[m][NN] = run;
        __syncthreads();
    }
}

__global__ void k_scatter(const int* __restrict__ src, const int* __restrict__ dst)
{
    int e = blockIdx.x*blockDim.x + threadIdx.x;
    if (e < EE) {
        int r = src[e];
        int p = g_ptr[0][r] + atomicAdd(&g_cur[0][r], 1);
        g_eidx[0][p] = e;
        r = dst[e];
        p = g_ptr[1][r] + atomicAdd(&g_cur[1][r], 1);
        g_eidx[1][p] = e;
    }
}

// ---- warp-per-row bitonic sort (64 elems) + fill + counter cleanup -----------
__global__ void k_sortfill(const int* __restrict__ src, const int* __restrict__ dst,
                           const float* __restrict__ v1, const float* __restrict__ v2)
{
    int m    = blockIdx.y;
    int wrp  = threadIdx.x >> 5;
    int lane = threadIdx.x & 31;
    int r    = blockIdx.x*8 + wrp;
    if (r >= NN) return;
    int beg = g_ptr[m][r], end = g_ptr[m][r+1];
    int deg = end - beg;

    // self-clean for next invocation (globals are zero-initialized at load)
    if (lane == 0) { g_cnt[m][r] = 0; g_cur[m][r] = 0; }

    if (deg <= 64) {
        const int BIG = 0x7fffffff;
        int e0 = (lane      < deg) ? g_eidx[m][beg + lane]      : BIG;
        int e1 = (lane + 32 < deg) ? g_eidx[m][beg + lane + 32] : BIG;

        #pragma unroll
        for (int k = 2; k <= 64; k <<= 1) {
            #pragma unroll
            for (int j = k >> 1; j > 0; j >>= 1) {
                if (j == 32) {
                    int lo = min(e0, e1), hi = max(e0, e1);
                    e0 = lo; e1 = hi;
                } else {
                    int p0 = __shfl_xor_sync(0xffffffffu, e0, j);
                    bool up0 = ((lane & k) == 0) || (k == 64);
                    bool km0 = (((lane & j) == 0) == up0);
                    e0 = km0 ? min(e0, p0) : max(e0, p0);
                    int p1 = __shfl_xor_sync(0xffffffffu, e1, j);
                    bool up1 = (k == 64) || (((lane + 32) & k) == 0);
                    bool km1 = (((lane & j) == 0) == up1);
                    e1 = km1 ? min(e1, p1) : max(e1, p1);
                }
            }
        }
        if (lane < deg) {
            int e = e0;
            int2 cw;
            if (m == 0) { cw.x = __ldg(dst+e); cw.y = __float_as_int(__ldg(v1+e)); }
            else        { cw.x = __ldg(src+e); cw.y = __float_as_int(__ldg(v2+e)); }
            g_cw[m][beg + lane] = cw;
        }
        if (lane + 32 < deg) {
            int e = e1;
            int2 cw;
            if (m == 0) { cw.x = __ldg(dst+e); cw.y = __float_as_int(__ldg(v1+e)); }
            else        { cw.x = __ldg(src+e); cw.y = __float_as_int(__ldg(v2+e)); }
            g_cw[m][beg + lane + 32] = cw;
        }
    } else if (lane == 0) {
        for (int i = beg+1; i < end; i++) {
            int key = g_eidx[m][i];
            int j = i-1;
            while (j >= beg && g_eidx[m][j] > key) { g_eidx[m][j+1] = g_eidx[m][j]; j--; }
            g_eidx[m][j+1] = key;
        }
        for (int i = beg; i < end; i++) {
            int e = g_eidx[m][i];
            int2 cw;
            if (m == 0) { cw.x = dst[e]; cw.y = __float_as_int(v1[e]); }
            else        { cw.x = src[e]; cw.y = __float_as_int(v2[e]); }
            g_cw[m][i] = cw;
        }
    }
}

// ---------------- SPMM: Y = A_m X (state rows + optional input rows) ---------
__device__ __forceinline__ void acc8(float* a, float w, uint4 h)
{
    float2 p0 = __half22float2(*(const __half2*)&h.x);
    float2 p1 = __half22float2(*(const __half2*)&h.y);
    float2 p2 = __half22float2(*(const __half2*)&h.z);
    float2 p3 = __half22float2(*(const __half2*)&h.w);
    a[0] += w*p0.x; a[1] += w*p0.y; a[2] += w*p1.x; a[3] += w*p1.y;
    a[4] += w*p2.x; a[5] += w*p2.y; a[6] += w*p3.x; a[7] += w*p3.y;
}
__device__ __forceinline__ uint4 pack8(const float* a)
{
    __half2 a0 = __floats2half2_rn(a[0],a[1]);
    __half2 a1 = __floats2half2_rn(a[2],a[3]);
    __half2 a2 = __floats2half2_rn(a[4],a[5]);
    __half2 a3 = __floats2half2_rn(a[6],a[7]);
    uint4 st; st.x=*(unsigned*)&a0; st.y=*(unsigned*)&a1; st.z=*(unsigned*)&a2; st.w=*(unsigned*)&a3;
    return st;
}

__global__ void __launch_bounds__(128) k_spmm(int xiA,int yiA,int xiB,int yiB)
{
    int m  = blockIdx.y;
    int xi = m ? xiB : xiA;
    int yi = m ? yiB : yiA;
    const int2* __restrict__ cw = g_cw[m];

    if (blockIdx.x < NN) {
        const uint4* __restrict__ X = (const uint4*)(g_Xs + (size_t)xi*NN*SROW);
        uint4*       __restrict__ Y = (uint4*)      (g_Xs + (size_t)yi*NN*SROW);
        int r = blockIdx.x;
        int t = threadIdx.x;
        int beg = g_ptr[m][r], end = g_ptr[m][r+1];

        float acc[8] = {0.f,0.f,0.f,0.f,0.f,0.f,0.f,0.f};
        int j = beg;
        for (; j + 8 <= end; j += 8) {
            int2 e[8];
            #pragma unroll
            for (int u = 0; u < 8; u++) e[u] = __ldg(cw + j + u);
            uint4 h[8];
            #pragma unroll
            for (int u = 0; u < 8; u++) h[u] = __ldg(X + (size_t)e[u].x*SV4 + t);
            #pragma unroll
            for (int u = 0; u < 8; u++) acc8(acc, __int_as_float(e[u].y), h[u]);
        }
        for (; j < end; j++) {
            int2 e = __ldg(cw + j);
            uint4 h = __ldg(X + (size_t)e.x*SV4 + t);
            acc8(acc, __int_as_float(e.y), h);
        }
        Y[(size_t)r*SV4 + t] = pack8(acc);
    } else {
        const uint4* __restrict__ X = (const uint4*)(g_Xin + (size_t)xi*NN*IROW);
        uint4*       __restrict__ Y = (uint4*)      (g_Xin + (size_t)yi*NN*IROW);
        int r = (blockIdx.x - NN)*32 + (threadIdx.x >> 2);
        int q = threadIdx.x & 3;
        int beg = g_ptr[m][r], end = g_ptr[m][r+1];
        float acc[8] = {0.f,0.f,0.f,0.f,0.f,0.f,0.f,0.f};
        for (int j = beg; j < end; j++) {
            int2 e = __ldg(cw + j);
            uint4 h = __ldg(X + (size_t)e.x*4 + q);
            acc8(acc, __int_as_float(e.y), h);
        }
        Y[(size_t)r*4 + q] = pack8(acc);
    }
}

// ---------------- MMA / ldmatrix helpers --------------------------------------
__device__ __forceinline__ void mma_16816(float c[4], const unsigned a[4], const unsigned b[2]) {
    asm volatile(
        "mma.sync.aligned.m16n8k16.row.col.f32.f16.f16.f32 "
        "{%0,%1,%2,%3},{%4,%5,%6,%7},{%8,%9},{%0,%1,%2,%3};\n"
        : "+f"(c[0]), "+f"(c[1]), "+f"(c[2]), "+f"(c[3])
        : "r"(a[0]), "r"(a[1]), "r"(a[2]), "r"(a[3]), "r"(b[0]), "r"(b[1]));
}
__device__ __forceinline__ void mma_1688(float c[4], const unsigned a[2], const unsigned b0) {
    asm volatile(
        "mma.sync.aligned.m16n8k8.row.col.f32.f16.f16.f32 "
        "{%0,%1,%2,%3},{%4,%5},{%6},{%0,%1,%2,%3};\n"
        : "+f"(c[0]), "+f"(c[1]), "+f"(c[2]), "+f"(c[3])
        : "r"(a[0]), "r"(a[1]), "r"(b0));
}
__device__ __forceinline__ unsigned su32(const void* p) {
    return (unsigned)__cvta_generic_to_shared(p);
}
__device__ __forceinline__ void ldsm4(unsigned* r, unsigned a) {
    asm volatile("ldmatrix.sync.aligned.m8n8.x4.shared.b16 {%0,%1,%2,%3},[%4];"
        : "=r"(r[0]),"=r"(r[1]),"=r"(r[2]),"=r"(r[3]) : "r"(a));
}
__device__ __forceinline__ void ldsm2(unsigned* r, unsigned a) {
    asm volatile("ldmatrix.sync.aligned.m8n8.x2.shared.b16 {%0,%1},[%2];"
        : "=r"(r[0]),"=r"(r[1]) : "r"(a));
}

// ---------------- gate GEMM (pipelined tile loads) + fused gating -------------
__global__ void __launch_bounds__(256) k_gemm_gate(const float* __restrict__ bg,
                                                   const float* __restrict__ state)
{
    __shared__ __align__(16) __half As[128][KP];
    __shared__ __align__(16) __half Bs[128][KP];

    int row0 = blockIdx.x * 128;
    int b  = row0 / NN;
    int n0 = row0 - b*NN;
    int tid = threadIdx.x;
    int wid = tid >> 5, lane = tid & 31;
    int q = lane & 3, rr_ = lane >> 2;
    int warp_m = wid & 3, warp_n = wid >> 2;

    unsigned Au[2], At[2], Bu[4], Bt[4];
    #pragma unroll
    for (int mt = 0; mt < 2; mt++) {
        Au[mt] = su32(&As[warp_m*32 + mt*16 + (lane & 15)][(lane >> 4)*8]);
        At[mt] = su32(&As[warp_m*32 + mt*16 + (lane & 15)][64]);
    }
    #pragma unroll
    for (int p = 0; p < 4; p++) {
        Bu[p] = su32(&Bs[warp_n*64 + p*16 + (lane & 7) + ((lane >> 4) & 1)*8][((lane >> 3) & 1)*8]);
        Bt[p] = su32(&Bs[warp_n*64 + p*16 + (lane & 7) + ((lane >> 3) & 1)*8][64]);
    }

    float acc[2][8][4];
    #pragma unroll
    for (int i = 0; i < 2; i++)
        #pragma unroll
        for (int j = 0; j < 8; j++)
            #pragma unroll
            for (int k = 0; k < 4; k++) acc[i][j][k] = 0.f;

    uint4 rv[9];
    auto load_tile = [&](int m, uint4* rv_) {
        const uint4* Xs  = (const uint4*)(g_Xs + (size_t)m*NN*SROW);
        const __half* Xin = g_Xin + (size_t)m*NN*IROW;
        const __half* Wm  = g_Wg_h + m*128*KP;
        #pragma unroll
        for (int u = 0; u < 9; u++) {
            int idx = tid + u*256;
            if (idx < 1152) {
                int rrow = idx / 9, j = idx - rrow*9;
                uint4 v;
                if (j < 8) v = Xs[(size_t)(n0+rrow)*SV4 + b*8 + j];
                else { v.x = *(const unsigned*)(Xin + (size_t)(n0+rrow)*IROW + b*2);
                       v.y = 0u; v.z = 0u; v.w = 0u; }
                rv_[u] = v;
            } else {
                int i2 = idx - 1152;
                int o = i2 / 9, j = i2 - o*9;
                rv_[u] = *(const uint4*)(Wm + o*KP + 8*j);
            }
        }
    };

    load_tile(0, rv);
    for (int m = 0; m < NMAT; m++) {
        __syncthreads();
        #pragma unroll
        for (int u = 0; u < 9; u++) {
            int idx = tid + u*256;
            if (idx < 1152) { int rrow = idx / 9, j = idx - rrow*9;
                              ((uint4*)&As[rrow][0])[j] = rv[u]; }
            else            { int i2 = idx - 1152; int o = i2 / 9, j = i2 - o*9;
                              ((uint4*)&Bs[o][0])[j] = rv[u]; }
        }
        __syncthreads();
        if (m < NMAT-1) load_tile(m+1, rv);

        #pragma unroll
        for (int ks = 0; ks < 4; ks++) {
            unsigned a0[4], a1[4];
            ldsm4(a0, Au[0] + ks*32);
            ldsm4(a1, Au[1] + ks*32);
            #pragma unroll
            for (int p = 0; p < 4; p++) {
                unsigned bb[4];
                ldsm4(bb, Bu[p] + ks*32);
                mma_16816(acc[0][2*p],   a0, bb);
                mma_16816(acc[0][2*p+1], a0, bb+2);
                mma_16816(acc[1][2*p],   a1, bb);
                mma_16816(acc[1][2*p+1], a1, bb+2);
            }
        }
        {
            unsigned a0[2], a1[2];
            ldsm2(a0, At[0]);
            ldsm2(a1, At[1]);
            #pragma unroll
            for (int p = 0; p < 4; p++) {
                unsigned bt[2];
                ldsm2(bt, Bt[p]);
                mma_1688(acc[0][2*p],   a0, bt[0]);
                mma_1688(acc[0][2*p+1], a0, bt[1]);
                mma_1688(acc[1][2*p],   a1, bt[0]);
                mma_1688(acc[1][2*p+1], a1, bt[1]);
            }
        }
    }

    __half* Xc0 = g_Xs + (size_t)5*NN*SROW;
    #pragma unroll
    for (int mt = 0; mt < 2; mt++) {
        #pragma unroll
        for (int nt = 0; nt < 8; nt++) {
            #pragma unroll
            for (int half_ : {0, 1}) {
                int row_l = warp_m*32 + mt*16 + rr_ + (half_ ? 8 : 0);
                int col   = warp_n*64 + nt*8 + 2*q;
                int n = n0 + row_l;
                float z0 = acc[mt][nt][2*half_+0] + bg[col];
                float z1 = acc[mt][nt][2*half_+1] + bg[col+1];
                float s0 = 1.f/(1.f + expf(-z0));
                float s1 = 1.f/(1.f + expf(-z1));
                if (col < HH) {
                    float2 st = *(const float2*)&state[(size_t)b*NN*HH + (size_t)n*HH + col];
                    __half2 rs = __floats2half2_rn(s0*st.x, s1*st.y);
                    *(__half2*)&Xc0[(size_t)n*SROW + b*HH + col] = rs;
                } else {
                    *(__half2*)&g_U[(size_t)(row0+row_l)*HH + (col-HH)] = __floats2half2_rn(s0, s1);
                }
            }
        }
    }
}

// ---------------- candidate GEMM (pipelined) + GRU combine --------------------
__global__ void __launch_bounds__(256) k_gemm_cand(const float* __restrict__ bc,
                                                   const float* __restrict__ state,
                                                   float* __restrict__ out, int dup)
{
    __shared__ __align__(16) __half As[128][KP];
    __shared__ __align__(16) __half Bs[64][KP];

    int row0 = blockIdx.x * 128;
    int b  = row0 / NN;
    int n0 = row0 - b*NN;
    int tid = threadIdx.x;
    int wid = tid >> 5, lane = tid & 31;
    int q = lane & 3, rr_ = lane >> 2;
    int warp_m = wid & 3, warp_n = wid >> 2;

    unsigned Au[2], At[2], Bu[2], Bt[2];
    #pragma unroll
    for (int mt = 0; mt < 2; mt++) {
        Au[mt] = su32(&As[warp_m*32 + mt*16 + (lane & 15)][(lane >> 4)*8]);
        At[mt] = su32(&As[warp_m*32 + mt*16 + (lane & 15)][64]);
    }
    #pragma unroll
    for (int p = 0; p < 2; p++) {
        Bu[p] = su32(&Bs[warp_n*32 + p*16 + (lane & 7) + ((lane >> 4) & 1)*8][((lane >> 3) & 1)*8]);
        Bt[p] = su32(&Bs[warp_n*32 + p*16 + (lane & 7) + ((lane >> 3) & 1)*8][64]);
    }

    float acc[2][4][4];
    #pragma unroll
    for (int i = 0; i < 2; i++)
        #pragma unroll
        for (int j = 0; j < 4; j++)
            #pragma unroll
            for (int k = 0; k < 4; k++) acc[i][j][k] = 0.f;

    uint4 rv[7];
    auto load_tile = [&](int m, uint4* rv_) {
        const uint4* Xs  = (const uint4*)(g_Xs + (size_t)(5+m)*NN*SROW);
        const __half* Xin = g_Xin + (size_t)m*NN*IROW;
        const __half* Wm  = g_Wc_h + m*64*KP;
        #pragma unroll
        for (int u = 0; u < 7; u++) {
            int idx = tid + u*256;
            if (idx < 1152) {
                int rrow = idx / 9, j = idx - rrow*9;
                uint4 v;
                if (j < 8) v = Xs[(size_t)(n0+rrow)*SV4 + b*8 + j];
                else { v.x = *(const unsigned*)(Xin + (size_t)(n0+rrow)*IROW + b*2);
                       v.y = 0u; v.z = 0u; v.w = 0u; }
                rv_[u] = v;
            } else if (idx < 1728) {
                int i2 = idx - 1152;
                int o = i2 / 9, j = i2 - o*9;
                rv_[u] = *(const uint4*)(Wm + o*KP + 8*j);
            }
        }
    };

    load_tile(0, rv);
    for (int m = 0; m < NMAT; m++) {
        __syncthreads();
        #pragma unroll
        for (int u = 0; u < 7; u++) {
            int idx = tid + u*256;
            if (idx < 1152) { int rrow = idx / 9, j = idx - rrow*9;
                              ((uint4*)&As[rrow][0])[j] = rv[u]; }
            else if (idx < 1728) { int i2 = idx - 1152; int o = i2 / 9, j = i2 - o*9;
                                   ((uint4*)&Bs[o][0])[j] = rv[u]; }
        }
        __syncthreads();
        if (m < NMAT-1) load_tile(m+1, rv);

        #pragma unroll
        for (int ks = 0; ks < 4; ks++) {
            unsigned a0[4], a1[4];
            ldsm4(a0, Au[0] + ks*32);
            ldsm4(a1, Au[1] + ks*32);
            #pragma unroll
            for (int p = 0; p < 2; p++) {
                unsigned bb[4];
                ldsm4(bb, Bu[p] + ks*32);
                mma_16816(acc[0][2*p],   a0, bb);
                mma_16816(acc[0][2*p+1], a0, bb+2);
                mma_16816(acc[1][2*p],   a1, bb);
                mma_16816(acc[1][2*p+1], a1, bb+2);
            }
        }
        {
            unsigned a0[2], a1[2];
            ldsm2(a0, At[0]);
            ldsm2(a1, At[1]);
            #pragma unroll
            for (int p = 0; p < 2; p++) {
                unsigned bt[2];
                ldsm2(bt, Bt[p]);
                mma_1688(acc[0][2*p],   a0, bt[0]);
                mma_1688(acc[0][2*p+1], a0, bt[1]);
                mma_1688(acc[1][2*p],   a1, bt[0]);
                mma_1688(acc[1][2*p+1], a1, bt[1]);
            }
        }
    }

    #pragma unroll
    for (int mt = 0; mt < 2; mt++) {
        #pragma unroll
        for (int nt = 0; nt < 4; nt++) {
            #pragma unroll
            for (int half_ : {0, 1}) {
                int row_l = warp_m*32 + mt*16 + rr_ + (half_ ? 8 : 0);
                int col   = warp_n*32 + nt*8 + 2*q;
                int n = n0 + row_l;
                int row = row0 + row_l;
                float c0 = tanhf(acc[mt][nt][2*half_+0] + bc[col]);
                float c1 = tanhf(acc[mt][nt][2*half_+1] + bc[col+1]);
                size_t sidx = (size_t)b*NN*HH + (size_t)n*HH + col;
                float2 u  = __half22float2(*(const __half2*)&g_U[(size_t)row*HH + col]);
                float2 st = *(const float2*)&state[sidx];
                float2 ns;
                ns.x = u.x*st.x + (1.f - u.x)*c0;
                ns.y = u.y*st.y + (1.f - u.y)*c1;
                *(float2*)&out[sidx] = ns;
                if (dup) *(float2*)&out[sidx + (size_t)BB*NN*HH] = ns;
            }
        }
    }
}

// ---------------- launch ------------------------------------------------------
extern "C" void kernel_launch(void* const* d_in, const int* in_sizes, int n_in,
                              void* d_out, int out_size)
{
    const float* inputs = (const float*)d_in[0];
    const float* state  = (const float*)d_in[1];
    const int*   esrc   = (const int*)  d_in[2];
    const int*   edst   = (const int*)  d_in[3];
    const float* v1     = (const float*)d_in[4];
    const float* v2     = (const float*)d_in[5];
    const float* Wg     = (const float*)d_in[6];
    const float* bg     = (const float*)d_in[7];
    const float* Wc     = (const float*)d_in[8];
    const float* bc     = (const float*)d_in[9];
    float* out = (float*)d_out;
    int dup = (out_size >= 2*BB*NN*HH) ? 1 : 0;

    // fused: edge-degree count (blocks < CNT_BLKS) + X/weight init (rest)
    k_count_init<<<CNT_BLKS + INIT_BLKS, 256>>>(esrc, edst, inputs, state, Wg, Wc);
    k_scan<<<1, 1024>>>();
    k_scatter<<<EE/256, 256>>>(esrc, edst);
    k_sortfill<<<dim3(NN/8,2), 256>>>(esrc, edst, v1, v2);   // also re-zeros cnt/cur

    k_spmm<<<dim3(NN+INBLK,2), 128>>>(0,1, 0,3);
    k_spmm<<<dim3(NN+INBLK,2), 128>>>(1,2, 3,4);

    k_gemm_gate<<<(BB*NN)/128, 256>>>(bg, state);

    k_spmm<<<dim3(NN,2), 128>>>(5,6, 5,8);
    k_spmm<<<dim3(NN,2), 128>>>(6,7, 8,9);

    k_gemm_cand<<<(BB*NN)/128, 256>>>(bc, state, out, dup);
}